// round 11
// baseline (speedup 1.0000x reference)
#include <cuda_runtime.h>
#include <cuda_bf16.h>
#include <mma.h>
#include <math.h>
#include <stdint.h>

using namespace nvcuda;

// ---------------- problem constants ----------------
#define BATCH   64
#define SEQ     197
#define TOK     (BATCH*SEQ)      // 12608
#define DIM     768
#define NHEAD   12
#define HDIM    64
#define HID     3072
#define BH      (BATCH*NHEAD)    // 768
#define LN_EPS  1e-6f

// padded attention dims
#define SEQP    208
#define KL      212              // pitch for t-contiguous rows (S, V^T)
#define VL      68               // pitch for d-contiguous rows (Q, K)

// ---------------- scratch (device globals) ----------------
__device__ float g_q  [(long)BH*SEQ*HDIM];
__device__ float g_k  [(long)BH*SEQ*HDIM];
__device__ float g_v  [(long)BH*SEQ*HDIM];
__device__ float g_ctx[(long)TOK*DIM];
__device__ float g_ao [(long)TOK*DIM];
__device__ float g_x1 [(long)TOK*DIM];
__device__ float g_x1r[(long)TOK*DIM];
__device__ float g_xr [(long)TOK*DIM];
__device__ float g_h  [(long)TOK*HID];
__device__ float g_mlp[(long)TOK*DIM];
// transposed + tf32-rounded weights: [N][K]
__device__ float g_wqT[DIM*DIM];
__device__ float g_wkT[DIM*DIM];
__device__ float g_wvT[DIM*DIM];
__device__ float g_woT[DIM*DIM];
__device__ float g_w1T[(long)HID*DIM];
__device__ float g_w2T[(long)DIM*HID];

__device__ __forceinline__ float tf32r(float x) { return wmma::__float_to_tf32(x); }
__device__ __forceinline__ float gelu_exact(float v) {
    return 0.5f * v * (1.f + erff(v * 0.70710678118654752f));
}
__device__ __forceinline__ void cpa16(uint32_t dst, const float* src) {
    asm volatile("cp.async.cg.shared.global [%0], [%1], 16;" :: "r"(dst), "l"(src) : "memory");
}
__device__ __forceinline__ void ldsm4(uint32_t addr, uint32_t& r0, uint32_t& r1,
                                      uint32_t& r2, uint32_t& r3) {
    asm volatile("ldmatrix.sync.aligned.m8n8.x4.shared.b16 {%0,%1,%2,%3}, [%4];"
                 : "=r"(r0), "=r"(r1), "=r"(r2), "=r"(r3) : "r"(addr));
}
__device__ __forceinline__ void mma_tf32(float* c, uint32_t a0, uint32_t a1,
                                         uint32_t a2, uint32_t a3,
                                         uint32_t b0, uint32_t b1) {
    asm volatile("mma.sync.aligned.m16n8k8.row.col.f32.tf32.tf32.f32 "
                 "{%0,%1,%2,%3}, {%4,%5,%6,%7}, {%8,%9}, {%0,%1,%2,%3};"
                 : "+f"(c[0]), "+f"(c[1]), "+f"(c[2]), "+f"(c[3])
                 : "r"(a0), "r"(a1), "r"(a2), "r"(a3), "r"(b0), "r"(b1));
}

// ---------------- tf32 RN rounding kernel (float4) ----------------
__global__ void round_k(const float* __restrict__ src, float* __restrict__ dst, int n4)
{
    int i = blockIdx.x*blockDim.x + threadIdx.x;
    if (i < n4) {
        float4 v = reinterpret_cast<const float4*>(src)[i];
        v.x = tf32r(v.x); v.y = tf32r(v.y); v.z = tf32r(v.z); v.w = tf32r(v.w);
        reinterpret_cast<float4*>(dst)[i] = v;
    }
}

// ---------------- transpose + tf32-round: src[K][N] -> dst[N][K] ----------------
// blockIdx.z picks one of two (src,dst) pairs so the prepass packs into fewer launches.
__global__ void troundT2_k(const float* __restrict__ s0, float* __restrict__ d0,
                           const float* __restrict__ s1, float* __restrict__ d1,
                           int K, int N)
{
    const float* src = blockIdx.z ? s1 : s0;
    float*       dst = blockIdx.z ? d1 : d0;
    __shared__ float t[32][33];
    const int n0 = blockIdx.x*32, k0 = blockIdx.y*32;
    const int tx = threadIdx.x & 31, tg = threadIdx.x >> 5;
    #pragma unroll
    for (int i=0;i<4;i++) {
        int r = tg + i*8;
        t[r][tx] = src[(size_t)(k0+r)*N + n0 + tx];
    }
    __syncthreads();
    #pragma unroll
    for (int i=0;i<4;i++) {
        int r = tg + i*8;
        dst[(size_t)(n0+r)*K + k0 + tx] = tf32r(t[tx][r]);
    }
}

// =====================================================================
// TF32 GEMM via ldmatrix + mma.m16n8k8.
// 128x128x32 tiles, 8 warps (64x32 warp tiles), 2 CTAs/SM.
// 3-stage cp.async pipeline, single __syncthreads per k-step.
// Register-direct epilogue (no smem staging).
// blockIdx.z selects (Bt, bias, D, alpha) -> fused QKV.
// =====================================================================
#define STAGE_FLOATS (256*36)                 // 9216
#define STAGE_BYTES  (STAGE_FLOATS*4)         // 36864
#define GEMM_SMEM_BYTES (3*STAGE_BYTES)       // 110592

template<int OUTMODE,int EPI,int ROUND>
__launch_bounds__(256, 2)
__global__ void tgemm_k(const float* __restrict__ A,
                        const float* __restrict__ B0, const float* __restrict__ B1, const float* __restrict__ B2,
                        const float* __restrict__ c0, const float* __restrict__ c1, const float* __restrict__ c2,
                        float* __restrict__ D0, float* __restrict__ D1, float* __restrict__ D2,
                        int M, int N, int K, float a0, float a1, float a2)
{
    extern __shared__ float sm[];
    const uint32_t smBase = (uint32_t)__cvta_generic_to_shared(sm);

    const int z = blockIdx.z;
    const float* Bt   = (z==0) ? B0 : (z==1) ? B1 : B2;
    const float* bias = (z==0) ? c0 : (z==1) ? c1 : c2;
    float*       C    = (z==0) ? D0 : (z==1) ? D1 : D2;
    const float alpha = (z==0) ? a0 : (z==1) ? a1 : a2;

    const int tileM = blockIdx.y * 128;
    const int tileN = blockIdx.x * 128;
    const int tid   = threadIdx.x;
    const int warpId= tid >> 5;
    const int lane  = tid & 31;
    const int wm    = warpId >> 2;      // 0..1
    const int wn    = warpId & 3;       // 0..3

    const int ldRow = tid >> 3;
    const int ldCol = (tid & 7) << 2;

    const float* aPtr[4];
    #pragma unroll
    for (int t=0;t<4;t++) {
        int gm = tileM + t*32 + ldRow;
        if (gm > M-1) gm = M-1;
        aPtr[t] = A + (size_t)gm*K + ldCol;
    }
    const float* bPtr[4];
    #pragma unroll
    for (int t=0;t<4;t++)
        bPtr[t] = Bt + (size_t)(tileN + t*32 + ldRow)*K + ldCol;

    const int aRowOff = (lane & 7) + ((lane >> 3) & 1) * 8;
    const int aKH     = (lane >> 4) * 4;
    const int bNOff   = (lane & 7) + (lane >> 4) * 8;
    const int bKH     = ((lane >> 3) & 1) * 4;

    const uint32_t aAddr0 = smBase + (uint32_t)(((wm*64 + aRowOff)*36 + aKH) * 4);
    const uint32_t bAddr0 = smBase + (uint32_t)((4608 + (wn*32 + bNOff)*36 + bKH) * 4);

    float acc[4][4][4];
    #pragma unroll
    for (int i=0;i<4;i++)
        #pragma unroll
        for (int j=0;j<4;j++)
            #pragma unroll
            for (int t=0;t<4;t++) acc[i][j][t] = 0.f;

    auto loadStage = [&](int k0, int st) {
        const uint32_t ab = smBase + (uint32_t)st*STAGE_BYTES;
        const uint32_t bb = ab + 4608u*4u;
        #pragma unroll
        for (int t=0;t<4;t++)
            cpa16(ab + (uint32_t)(((t*32 + ldRow)*36 + ldCol)*4), aPtr[t] + k0);
        #pragma unroll
        for (int t=0;t<4;t++)
            cpa16(bb + (uint32_t)(((t*32 + ldRow)*36 + ldCol)*4), bPtr[t] + k0);
        asm volatile("cp.async.commit_group;" ::: "memory");
    };

    const int NS = K >> 5;
    loadStage(0, 0);
    if (NS > 1) loadStage(32, 1);

    int st = 0;
    for (int s = 0; s < NS; s++) {
        if (s + 1 < NS) asm volatile("cp.async.wait_group 1;" ::: "memory");
        else            asm volatile("cp.async.wait_group 0;" ::: "memory");
        __syncthreads();

        if (s + 2 < NS) {
            int nst = st + 2; if (nst >= 3) nst -= 3;
            loadStage((s+2) << 5, nst);
        }

        const uint32_t aS = aAddr0 + (uint32_t)st*STAGE_BYTES;
        const uint32_t bS = bAddr0 + (uint32_t)st*STAGE_BYTES;
        #pragma unroll
        for (int ks=0; ks<4; ks++) {
            uint32_t a[4][4], b[2][4];
            #pragma unroll
            for (int mb=0; mb<4; mb++)
                ldsm4(aS + (uint32_t)(mb*16*36*4 + ks*32), a[mb][0], a[mb][1], a[mb][2], a[mb][3]);
            #pragma unroll
            for (int nb=0; nb<2; nb++)
                ldsm4(bS + (uint32_t)(nb*16*36*4 + ks*32), b[nb][0], b[nb][1], b[nb][2], b[nb][3]);
            #pragma unroll
            for (int mb=0; mb<4; mb++)
                #pragma unroll
                for (int j=0; j<4; j++)
                    mma_tf32(acc[mb][j], a[mb][0], a[mb][1], a[mb][2], a[mb][3],
                             b[j>>1][(j&1)*2], b[j>>1][(j&1)*2+1]);
        }
        if (++st == 3) st = 0;
    }

    // ---- register-direct epilogue: float2 stores, no smem staging ----
    {
        const int r0 = lane >> 2;            // 0..7
        const int cb = 2*(lane & 3);         // 0,2,4,6
        // per-j column data (bias) hoisted out of the mb loop
        float bx[4], by[4];
        int   gn4[4];
        #pragma unroll
        for (int j=0;j<4;j++) {
            int gn = tileN + wn*32 + j*8 + cb;
            gn4[j] = gn;
            bx[j] = bias[gn];
            by[j] = bias[gn+1];
        }
        #pragma unroll
        for (int mb=0; mb<4; mb++) {
            #pragma unroll
            for (int half=0; half<2; half++) {
                int gm = tileM + wm*64 + mb*16 + r0 + half*8;
                if (gm >= M) continue;
                size_t rowBase;
                int bb_ = 0, ss_ = 0;
                if (OUTMODE == 1) { bb_ = gm / SEQ; ss_ = gm - bb_*SEQ; }
                else rowBase = (size_t)gm * N;
                #pragma unroll
                for (int j=0; j<4; j++) {
                    float vx = (acc[mb][j][half*2]   + bx[j]) * alpha;
                    float vy = (acc[mb][j][half*2+1] + by[j]) * alpha;
                    if (EPI == 1) { vx = gelu_exact(vx); vy = gelu_exact(vy); }
                    if (ROUND)    { vx = tf32r(vx);      vy = tf32r(vy); }
                    if (OUTMODE == 0) {
                        *reinterpret_cast<float2*>(&C[(size_t)gm*N + gn4[j]]) = make_float2(vx, vy);
                    } else {
                        int h = gn4[j] >> 6, dd = gn4[j] & 63;
                        size_t orow = (size_t)(bb_*NHEAD + h)*SEQ + ss_;
                        *reinterpret_cast<float2*>(&C[orow*HDIM + dd]) = make_float2(vx, vy);
                    }
                }
            }
        }
    }
}

// =====================================================================
// Fused attention: one CTA per (bh, s-tile). 512 threads (16 warps).
// =====================================================================
#define OFF_K   0
#define OFF_V   (SEQP*VL)
#define OFF_QO  (OFF_V + 64*KL)
#define OFF_S   (OFF_QO + 64*VL)
#define ATTN_SMEM_FLOATS (OFF_S + 64*KL)
#define ATTN_SMEM_BYTES  (ATTN_SMEM_FLOATS*4)

__launch_bounds__(512)
__global__ void attn_k(const float* __restrict__ q, const float* __restrict__ k,
                       const float* __restrict__ v, float* __restrict__ ctx)
{
    extern __shared__ float sm[];
    const uint32_t smBase = (uint32_t)__cvta_generic_to_shared(sm);
    float* Ksm = sm + OFF_K;
    float* Vsm = sm + OFF_V;
    float* QO  = sm + OFF_QO;
    float* Ssm = sm + OFF_S;

    const int bh   = blockIdx.x >> 2;
    const int tile = blockIdx.x & 3;
    const int s0   = tile * 64;
    const int valid = (SEQ - s0) < 64 ? (SEQ - s0) : 64;
    const int miMax = (valid + 15) >> 4;

    const int b  = bh / NHEAD;
    const int h  = bh - b*NHEAD;
    const int tid    = threadIdx.x;
    const int warpId = tid >> 5;
    const int lane   = tid & 31;

    const float* qb = q + (size_t)bh*SEQ*HDIM;
    const float* kb = k + (size_t)bh*SEQ*HDIM;
    const float* vb = v + (size_t)bh*SEQ*HDIM;

    const int aRowOff = (lane & 7) + ((lane >> 3) & 1) * 8;
    const int aKH     = (lane >> 4) * 4;
    const int bNOff   = (lane & 7) + (lane >> 4) * 8;
    const int bKH     = ((lane >> 3) & 1) * 4;
    const int r0 = lane >> 2;
    const int cb = 2*(lane & 3);

    for (int idx = tid; idx < SEQP*16; idx += 512) {
        int t = idx >> 4, f = idx & 15;
        float4 val = (t < SEQ) ? *reinterpret_cast<const float4*>(&kb[(size_t)t*HDIM + f*4])
                               : make_float4(0.f,0.f,0.f,0.f);
        *reinterpret_cast<float4*>(&Ksm[t*VL + f*4]) = val;
    }
    for (int idx = tid; idx < SEQP*HDIM; idx += 512) {
        int t = idx >> 6, d = idx & 63;
        Vsm[d*KL + t] = (t < SEQ) ? vb[(size_t)t*HDIM + d] : 0.f;
    }
    for (int idx = tid; idx < 64*16; idx += 512) {
        int r = idx >> 4, f = idx & 15;
        int s = s0 + r;
        float4 val = (s < SEQ) ? *reinterpret_cast<const float4*>(&qb[(size_t)s*HDIM + f*4])
                               : make_float4(0.f,0.f,0.f,0.f);
        *reinterpret_cast<float4*>(&QO[r*VL + f*4]) = val;
    }
    __syncthreads();

    for (int t = warpId; t < miMax*13; t += 16) {
        int mi = t / 13, ni = t - (t/13)*13;
        float c0[4] = {0.f,0.f,0.f,0.f}, c1[4] = {0.f,0.f,0.f,0.f};
        const uint32_t aAddr = smBase + (uint32_t)((OFF_QO + (mi*16 + aRowOff)*VL + aKH)*4);
        const uint32_t bAddr = smBase + (uint32_t)((OFF_K  + (ni*16 + bNOff)*VL + bKH)*4);
        #pragma unroll
        for (int ks=0; ks<8; ks++) {
            uint32_t a0,a1,a2,a3, b0,b1,b2,b3;
            ldsm4(aAddr + ks*32, a0,a1,a2,a3);
            ldsm4(bAddr + ks*32, b0,b1,b2,b3);
            mma_tf32(c0, a0,a1,a2,a3, b0,b1);
            mma_tf32(c1, a0,a1,a2,a3, b2,b3);
        }
        {
            int row = mi*16 + r0, col = ni*16 + cb;
            *reinterpret_cast<float2*>(&Ssm[row*KL + col])         = make_float2(c0[0], c0[1]);
            *reinterpret_cast<float2*>(&Ssm[(row+8)*KL + col])     = make_float2(c0[2], c0[3]);
            *reinterpret_cast<float2*>(&Ssm[row*KL + col + 8])     = make_float2(c1[0], c1[1]);
            *reinterpret_cast<float2*>(&Ssm[(row+8)*KL + col + 8]) = make_float2(c1[2], c1[3]);
        }
    }
    __syncthreads();

    for (int rr = 0; rr < miMax; rr++) {
        int r = rr*16 + warpId;
        if (r >= miMax*16) break;
        float* rowp = &Ssm[r*KL];
        float x[7];
        float m = -1e30f;
        #pragma unroll
        for (int i=0;i<7;i++) {
            int c = lane + i*32;
            x[i] = (c < SEQ) ? rowp[c] : -1e30f;
            m = fmaxf(m, x[i]);
        }
        #pragma unroll
        for (int o=16;o;o>>=1) m = fmaxf(m, __shfl_xor_sync(0xffffffffu, m, o));
        float sum = 0.f;
        #pragma unroll
        for (int i=0;i<7;i++) { x[i] = __expf(x[i] - m); sum += x[i]; }
        #pragma unroll
        for (int o=16;o;o>>=1) sum += __shfl_xor_sync(0xffffffffu, sum, o);
        float inv = 1.f / sum;
        #pragma unroll
        for (int i=0;i<7;i++) {
            int c = lane + i*32;
            if (c < SEQ)       rowp[c] = tf32r(x[i]*inv);
            else if (c < SEQP) rowp[c] = 0.f;
        }
    }
    __syncthreads();

    if (warpId < miMax*4) {
        int mi = warpId >> 2, ni = warpId & 3;
        float c0[4] = {0.f,0.f,0.f,0.f}, c1[4] = {0.f,0.f,0.f,0.f};
        const uint32_t aAddr = smBase + (uint32_t)((OFF_S + (mi*16 + aRowOff)*KL + aKH)*4);
        const uint32_t bAddr = smBase + (uint32_t)((OFF_V + (ni*16 + bNOff)*KL + bKH)*4);
        #pragma unroll
        for (int ks=0; ks<26; ks++) {
            uint32_t a0,a1,a2,a3, b0,b1,b2,b3;
            ldsm4(aAddr + ks*32, a0,a1,a2,a3);
            ldsm4(bAddr + ks*32, b0,b1,b2,b3);
            mma_tf32(c0, a0,a1,a2,a3, b0,b1);
            mma_tf32(c1, a0,a1,a2,a3, b2,b3);
        }
        {
            int row = mi*16 + r0, col = ni*16 + cb;
            *reinterpret_cast<float2*>(&QO[row*VL + col])         = make_float2(c0[0], c0[1]);
            *reinterpret_cast<float2*>(&QO[(row+8)*VL + col])     = make_float2(c0[2], c0[3]);
            *reinterpret_cast<float2*>(&QO[row*VL + col + 8])     = make_float2(c1[0], c1[1]);
            *reinterpret_cast<float2*>(&QO[(row+8)*VL + col + 8]) = make_float2(c1[2], c1[3]);
        }
    }
    __syncthreads();

    for (int idx = tid; idx < valid*16; idx += 512) {
        int r = idx >> 4, f = idx & 15;
        int s = s0 + r;
        float4 val = *reinterpret_cast<const float4*>(&QO[r*VL + f*4]);
        val.x=tf32r(val.x); val.y=tf32r(val.y); val.z=tf32r(val.z); val.w=tf32r(val.w);
        *reinterpret_cast<float4*>(&ctx[((size_t)(b*SEQ + s))*DIM + h*HDIM + f*4]) = val;
    }
}

// ---------------- residual + LayerNorm (float4 vectorized) ----------------
__launch_bounds__(192)
__global__ void add_ln_k(const float* __restrict__ x, const float* __restrict__ y,
                         const float* __restrict__ g, const float* __restrict__ be,
                         float* __restrict__ out, float* __restrict__ outR)
{
    const int r = blockIdx.x;
    const int t = threadIdx.x;
    const float4 yv = *reinterpret_cast<const float4*>(&y[(size_t)r*DIM + t*4]);

    float s  = yv.x + yv.y + yv.z + yv.w;
    float sq = yv.x*yv.x + yv.y*yv.y + yv.z*yv.z + yv.w*yv.w;

    __shared__ float red[12];
    #pragma unroll
    for (int o=16;o;o>>=1) { s += __shfl_xor_sync(0xffffffffu, s, o); sq += __shfl_xor_sync(0xffffffffu, sq, o); }
    int w = t >> 5, lane = t & 31;
    if (lane == 0) { red[w] = s; red[w+6] = sq; }
    __syncthreads();
    if (t < 32) {
        s  = (lane < 6) ? red[lane]     : 0.f;
        sq = (lane < 6) ? red[lane + 6] : 0.f;
        #pragma unroll
        for (int o=4;o;o>>=1) { s += __shfl_xor_sync(0xffffffffu, s, o); sq += __shfl_xor_sync(0xffffffffu, sq, o); }
        if (lane == 0) { red[0] = s; red[1] = sq; }
    }
    __syncthreads();
    const float mu   = red[0] * (1.f/DIM);
    const float var  = red[1] * (1.f/DIM) - mu*mu;
    const float rstd = rsqrtf(var + LN_EPS);

    const float4 xv = *reinterpret_cast<const float4*>(&x[(size_t)r*DIM + t*4]);
    const float4 gv = *reinterpret_cast<const float4*>(&g[t*4]);
    const float4 bv = *reinterpret_cast<const float4*>(&be[t*4]);
    float4 o;
    o.x = xv.x + (yv.x - mu)*rstd*gv.x + bv.x;
    o.y = xv.y + (yv.y - mu)*rstd*gv.y + bv.y;
    o.z = xv.z + (yv.z - mu)*rstd*gv.z + bv.z;
    o.w = xv.w + (yv.w - mu)*rstd*gv.w + bv.w;
    *reinterpret_cast<float4*>(&out[(size_t)r*DIM + t*4]) = o;
    if (outR) {
        float4 orr;
        orr.x = tf32r(o.x); orr.y = tf32r(o.y); orr.z = tf32r(o.z); orr.w = tf32r(o.w);
        *reinterpret_cast<float4*>(&outR[(size_t)r*DIM + t*4]) = orr;
    }
}

// ---------------- launch ----------------
extern "C" void kernel_launch(void* const* d_in, const int* in_sizes, int n_in,
                              void* d_out, int out_size)
{
    const float* x   = (const float*)d_in[0];
    const float* Wq  = (const float*)d_in[1];
    const float* bq  = (const float*)d_in[2];
    const float* Wk  = (const float*)d_in[3];
    const float* bk  = (const float*)d_in[4];
    const float* Wv  = (const float*)d_in[5];
    const float* bv  = (const float*)d_in[6];
    const float* Wo  = (const float*)d_in[7];
    const float* bo  = (const float*)d_in[8];
    const float* W1  = (const float*)d_in[9];
    const float* b1  = (const float*)d_in[10];
    const float* W2  = (const float*)d_in[11];
    const float* b2  = (const float*)d_in[12];
    const float* g1  = (const float*)d_in[13];
    const float* be1 = (const float*)d_in[14];
    const float* g2  = (const float*)d_in[15];
    const float* be2 = (const float*)d_in[16];
    float* out = (float*)d_out;

    float *q,*k,*v,*ctx,*ao,*x1,*x1r,*xr,*hh,*mlp;
    float *wqT,*wkT,*wvT,*woT,*w1T,*w2T;
    cudaGetSymbolAddress((void**)&q,   g_q);
    cudaGetSymbolAddress((void**)&k,   g_k);
    cudaGetSymbolAddress((void**)&v,   g_v);
    cudaGetSymbolAddress((void**)&ctx, g_ctx);
    cudaGetSymbolAddress((void**)&ao,  g_ao);
    cudaGetSymbolAddress((void**)&x1,  g_x1);
    cudaGetSymbolAddress((void**)&x1r, g_x1r);
    cudaGetSymbolAddress((void**)&xr,  g_xr);
    cudaGetSymbolAddress((void**)&hh,  g_h);
    cudaGetSymbolAddress((void**)&mlp, g_mlp);
    cudaGetSymbolAddress((void**)&wqT, g_wqT);
    cudaGetSymbolAddress((void**)&wkT, g_wkT);
    cudaGetSymbolAddress((void**)&wvT, g_wvT);
    cudaGetSymbolAddress((void**)&woT, g_woT);
    cudaGetSymbolAddress((void**)&w1T, g_w1T);
    cudaGetSymbolAddress((void**)&w2T, g_w2T);

    cudaFuncSetAttribute(tgemm_k<1,0,1>, cudaFuncAttributeMaxDynamicSharedMemorySize, GEMM_SMEM_BYTES);
    cudaFuncSetAttribute(tgemm_k<0,0,0>, cudaFuncAttributeMaxDynamicSharedMemorySize, GEMM_SMEM_BYTES);
    cudaFuncSetAttribute(tgemm_k<0,1,1>, cudaFuncAttributeMaxDynamicSharedMemorySize, GEMM_SMEM_BYTES);
    cudaFuncSetAttribute(attn_k,         cudaFuncAttributeMaxDynamicSharedMemorySize, ATTN_SMEM_BYTES);

    // --- pre-pass (5 launches, so launch #5 = QKV GEMM for ncu -s 5) ---
    {
        int n = TOK*DIM/4;
        round_k<<<(n+255)/256, 256>>>(x, xr, n);                       // launch 0
        dim3 tg(DIM/32, DIM/32, 2);
        troundT2_k<<<tg, 256>>>(Wq, wqT, Wk, wkT, DIM, DIM);           // launch 1
        troundT2_k<<<tg, 256>>>(Wv, wvT, Wo, woT, DIM, DIM);           // launch 2
        dim3 tg1(HID/32, DIM/32, 1);
        troundT2_k<<<tg1, 256>>>(W1, w1T, W1, w1T, DIM, HID);          // launch 3
        dim3 tg2(DIM/32, HID/32, 1);
        troundT2_k<<<tg2, 256>>>(W2, w2T, W2, w2T, HID, DIM);          // launch 4
    }

    const int mtiles = (TOK + 127)/128;   // 99

    // --- fused QKV projection (launch 5 -> ncu target) ---
    {
        dim3 grid(DIM/128, mtiles, 3);
        tgemm_k<1,0,1><<<grid, 256, GEMM_SMEM_BYTES>>>(xr, wqT, wkT, wvT, bq, bk, bv,
                                                       q, k, v, TOK, DIM, DIM,
                                                       0.125f, 1.0f, 1.0f);
    }

    // --- fused attention -> ctx (rounded) ---
    attn_k<<<BH*4, 512, ATTN_SMEM_BYTES>>>(q, k, v, ctx);

    // --- attn_out = ctx @ Wo + bo ---
    {
        dim3 grid(DIM/128, mtiles, 1);
        tgemm_k<0,0,0><<<grid, 256, GEMM_SMEM_BYTES>>>(ctx, woT, woT, woT, bo, bo, bo,
                                                       ao, ao, ao, TOK, DIM, DIM,
                                                       1.0f, 1.0f, 1.0f);
    }

    // --- x1 = x + LN(attn_out); rounded copy for MLP1 ---
    add_ln_k<<<TOK, 192>>>(x, ao, g1, be1, x1, x1r);

    // --- h = gelu(x1 @ W1 + b1) (rounded) ---
    {
        dim3 grid(HID/128, mtiles, 1);
        tgemm_k<0,1,1><<<grid, 256, GEMM_SMEM_BYTES>>>(x1r, w1T, w1T, w1T, b1, b1, b1,
                                                       hh, hh, hh, TOK, HID, DIM,
                                                       1.0f, 1.0f, 1.0f);
    }

    // --- mlp = h @ W2 + b2 ---
    {
        dim3 grid(DIM/128, mtiles, 1);
        tgemm_k<0,0,0><<<grid, 256, GEMM_SMEM_BYTES>>>(hh, w2T, w2T, w2T, b2, b2, b2,
                                                       mlp, mlp, mlp, TOK, DIM, HID,
                                                       1.0f, 1.0f, 1.0f);
    }

    // --- out = x1 + LN(mlp) ---
    add_ln_k<<<TOK, 192>>>(x1, mlp, g2, be2, out, nullptr);
}

// round 12
// speedup vs baseline: 1.3848x; 1.3848x over previous
#include <cuda_runtime.h>
#include <cuda_bf16.h>
#include <mma.h>
#include <math.h>
#include <stdint.h>

using namespace nvcuda;

// ---------------- problem constants ----------------
#define BATCH   64
#define SEQ     197
#define TOK     (BATCH*SEQ)      // 12608
#define DIM     768
#define NHEAD   12
#define HDIM    64
#define HID     3072
#define BH      (BATCH*NHEAD)    // 768
#define LN_EPS  1e-6f

// padded attention dims
#define SEQP    208
#define KL      212              // pitch for t-contiguous rows (S, V^T)
#define VL      68               // pitch for d-contiguous rows (Q, K)

// ---------------- scratch (device globals) ----------------
__device__ float g_q  [(long)BH*SEQ*HDIM];
__device__ float g_k  [(long)BH*SEQ*HDIM];
__device__ float g_v  [(long)BH*SEQ*HDIM];
__device__ float g_ctx[(long)TOK*DIM];
__device__ float g_ao [(long)TOK*DIM];
__device__ float g_x1 [(long)TOK*DIM];
__device__ float g_x1r[(long)TOK*DIM];
__device__ float g_xr [(long)TOK*DIM];
__device__ float g_h  [(long)TOK*HID];
__device__ float g_mlp[(long)TOK*DIM];
// transposed + tf32-rounded weights: [N][K]
__device__ float g_wqT[DIM*DIM];
__device__ float g_wkT[DIM*DIM];
__device__ float g_wvT[DIM*DIM];
__device__ float g_woT[DIM*DIM];
__device__ float g_w1T[(long)HID*DIM];
__device__ float g_w2T[(long)DIM*HID];

__device__ __forceinline__ float tf32r(float x) { return wmma::__float_to_tf32(x); }
__device__ __forceinline__ float gelu_exact(float v) {
    return 0.5f * v * (1.f + erff(v * 0.70710678118654752f));
}
__device__ __forceinline__ void cpa16(uint32_t dst, const float* src) {
    asm volatile("cp.async.cg.shared.global [%0], [%1], 16;" :: "r"(dst), "l"(src) : "memory");
}
__device__ __forceinline__ void ldsm4(uint32_t addr, uint32_t& r0, uint32_t& r1,
                                      uint32_t& r2, uint32_t& r3) {
    asm volatile("ldmatrix.sync.aligned.m8n8.x4.shared.b16 {%0,%1,%2,%3}, [%4];"
                 : "=r"(r0), "=r"(r1), "=r"(r2), "=r"(r3) : "r"(addr));
}
__device__ __forceinline__ void mma_tf32(float* c, uint32_t a0, uint32_t a1,
                                         uint32_t a2, uint32_t a3,
                                         uint32_t b0, uint32_t b1) {
    asm volatile("mma.sync.aligned.m16n8k8.row.col.f32.tf32.tf32.f32 "
                 "{%0,%1,%2,%3}, {%4,%5,%6,%7}, {%8,%9}, {%0,%1,%2,%3};"
                 : "+f"(c[0]), "+f"(c[1]), "+f"(c[2]), "+f"(c[3])
                 : "r"(a0), "r"(a1), "r"(a2), "r"(a3), "r"(b0), "r"(b1));
}

// ---------------- tf32 RN rounding kernel (float4) ----------------
__global__ void round_k(const float* __restrict__ src, float* __restrict__ dst, int n4)
{
    int i = blockIdx.x*blockDim.x + threadIdx.x;
    if (i < n4) {
        float4 v = reinterpret_cast<const float4*>(src)[i];
        v.x = tf32r(v.x); v.y = tf32r(v.y); v.z = tf32r(v.z); v.w = tf32r(v.w);
        reinterpret_cast<float4*>(dst)[i] = v;
    }
}

// ---------------- transpose + tf32-round: src[K][N] -> dst[N][K] ----------------
// blockIdx.z picks one of two (src,dst) pairs (same K,N for both).
__global__ void troundT2_k(const float* __restrict__ s0, float* __restrict__ d0,
                           const float* __restrict__ s1, float* __restrict__ d1,
                           int K, int N)
{
    const float* src = blockIdx.z ? s1 : s0;
    float*       dst = blockIdx.z ? d1 : d0;
    __shared__ float t[32][33];
    const int n0 = blockIdx.x*32, k0 = blockIdx.y*32;
    const int tx = threadIdx.x & 31, tg = threadIdx.x >> 5;
    #pragma unroll
    for (int i=0;i<4;i++) {
        int r = tg + i*8;
        t[r][tx] = src[(size_t)(k0+r)*N + n0 + tx];
    }
    __syncthreads();
    #pragma unroll
    for (int i=0;i<4;i++) {
        int r = tg + i*8;
        dst[(size_t)(n0+r)*K + k0 + tx] = tf32r(t[tx][r]);
    }
}

// ---------------- combined W1/W2 transpose (different shapes per z) ----------------
// z=0: src[DIM][HID] -> dst[HID][DIM]   (x < HID/32, y < DIM/32)
// z=1: src[HID][DIM] -> dst[DIM][HID]   (x < DIM/32, y < HID/32)
__global__ void troundT12_k(const float* __restrict__ s0, float* __restrict__ d0,
                            const float* __restrict__ s1, float* __restrict__ d1)
{
    int K, N;
    const float* src;
    float* dst;
    if (blockIdx.z == 0) {
        if (blockIdx.x >= HID/32 || blockIdx.y >= DIM/32) return;
        src = s0; dst = d0; K = DIM; N = HID;
    } else {
        if (blockIdx.x >= DIM/32 || blockIdx.y >= HID/32) return;
        src = s1; dst = d1; K = HID; N = DIM;
    }
    __shared__ float t[32][33];
    const int n0 = blockIdx.x*32, k0 = blockIdx.y*32;
    const int tx = threadIdx.x & 31, tg = threadIdx.x >> 5;
    #pragma unroll
    for (int i=0;i<4;i++) {
        int r = tg + i*8;
        t[r][tx] = src[(size_t)(k0+r)*N + n0 + tx];
    }
    __syncthreads();
    #pragma unroll
    for (int i=0;i<4;i++) {
        int r = tg + i*8;
        dst[(size_t)(n0+r)*K + k0 + tx] = tf32r(t[tx][r]);
    }
}

// =====================================================================
// TF32 GEMM via ldmatrix + mma.m16n8k8. (R10 configuration, proven)
// 128x128x32 tiles, 8 warps (64x32 warp tiles), 2 CTAs/SM.
// 3-stage cp.async pipeline, single __syncthreads per k-step.
// Smem-staged epilogue with coalesced float4 stores.
// blockIdx.z selects (Bt, bias, D, alpha) -> fused QKV.
// =====================================================================
#define STAGE_FLOATS (256*36)                 // 9216
#define STAGE_BYTES  (STAGE_FLOATS*4)         // 36864
#define GEMM_SMEM_BYTES (3*STAGE_BYTES)       // 110592; epilogue 128*132*4=67584 fits

template<int OUTMODE,int EPI,int ROUND>
__launch_bounds__(256, 2)
__global__ void tgemm_k(const float* __restrict__ A,
                        const float* __restrict__ B0, const float* __restrict__ B1, const float* __restrict__ B2,
                        const float* __restrict__ c0, const float* __restrict__ c1, const float* __restrict__ c2,
                        float* __restrict__ D0, float* __restrict__ D1, float* __restrict__ D2,
                        int M, int N, int K, float a0, float a1, float a2)
{
    extern __shared__ float sm[];
    const uint32_t smBase = (uint32_t)__cvta_generic_to_shared(sm);

    const int z = blockIdx.z;
    const float* Bt   = (z==0) ? B0 : (z==1) ? B1 : B2;
    const float* bias = (z==0) ? c0 : (z==1) ? c1 : c2;
    float*       C    = (z==0) ? D0 : (z==1) ? D1 : D2;
    const float alpha = (z==0) ? a0 : (z==1) ? a1 : a2;

    const int tileM = blockIdx.y * 128;
    const int tileN = blockIdx.x * 128;
    const int tid   = threadIdx.x;
    const int warpId= tid >> 5;
    const int lane  = tid & 31;
    const int wm    = warpId >> 2;      // 0..1
    const int wn    = warpId & 3;       // 0..3

    const int ldRow = tid >> 3;
    const int ldCol = (tid & 7) << 2;

    const float* aPtr[4];
    #pragma unroll
    for (int t=0;t<4;t++) {
        int gm = tileM + t*32 + ldRow;
        if (gm > M-1) gm = M-1;
        aPtr[t] = A + (size_t)gm*K + ldCol;
    }
    const float* bPtr[4];
    #pragma unroll
    for (int t=0;t<4;t++)
        bPtr[t] = Bt + (size_t)(tileN + t*32 + ldRow)*K + ldCol;

    const int aRowOff = (lane & 7) + ((lane >> 3) & 1) * 8;
    const int aKH     = (lane >> 4) * 4;
    const int bNOff   = (lane & 7) + (lane >> 4) * 8;
    const int bKH     = ((lane >> 3) & 1) * 4;

    const uint32_t aAddr0 = smBase + (uint32_t)(((wm*64 + aRowOff)*36 + aKH) * 4);
    const uint32_t bAddr0 = smBase + (uint32_t)((4608 + (wn*32 + bNOff)*36 + bKH) * 4);

    float acc[4][4][4];
    #pragma unroll
    for (int i=0;i<4;i++)
        #pragma unroll
        for (int j=0;j<4;j++)
            #pragma unroll
            for (int t=0;t<4;t++) acc[i][j][t] = 0.f;

    auto loadStage = [&](int k0, int st) {
        const uint32_t ab = smBase + (uint32_t)st*STAGE_BYTES;
        const uint32_t bb = ab + 4608u*4u;
        #pragma unroll
        for (int t=0;t<4;t++)
            cpa16(ab + (uint32_t)(((t*32 + ldRow)*36 + ldCol)*4), aPtr[t] + k0);
        #pragma unroll
        for (int t=0;t<4;t++)
            cpa16(bb + (uint32_t)(((t*32 + ldRow)*36 + ldCol)*4), bPtr[t] + k0);
        asm volatile("cp.async.commit_group;" ::: "memory");
    };

    const int NS = K >> 5;
    loadStage(0, 0);
    if (NS > 1) loadStage(32, 1);

    int st = 0;
    for (int s = 0; s < NS; s++) {
        if (s + 1 < NS) asm volatile("cp.async.wait_group 1;" ::: "memory");
        else            asm volatile("cp.async.wait_group 0;" ::: "memory");
        __syncthreads();

        if (s + 2 < NS) {
            int nst = st + 2; if (nst >= 3) nst -= 3;
            loadStage((s+2) << 5, nst);
        }

        const uint32_t aS = aAddr0 + (uint32_t)st*STAGE_BYTES;
        const uint32_t bS = bAddr0 + (uint32_t)st*STAGE_BYTES;
        #pragma unroll
        for (int ks=0; ks<4; ks++) {
            uint32_t a[4][4], b[2][4];
            #pragma unroll
            for (int mb=0; mb<4; mb++)
                ldsm4(aS + (uint32_t)(mb*16*36*4 + ks*32), a[mb][0], a[mb][1], a[mb][2], a[mb][3]);
            #pragma unroll
            for (int nb=0; nb<2; nb++)
                ldsm4(bS + (uint32_t)(nb*16*36*4 + ks*32), b[nb][0], b[nb][1], b[nb][2], b[nb][3]);
            #pragma unroll
            for (int mb=0; mb<4; mb++)
                #pragma unroll
                for (int j=0; j<4; j++)
                    mma_tf32(acc[mb][j], a[mb][0], a[mb][1], a[mb][2], a[mb][3],
                             b[j>>1][(j&1)*2], b[j>>1][(j&1)*2+1]);
        }
        if (++st == 3) st = 0;
    }
    __syncthreads();

    // ---- epilogue: stage 128x128 tile in smem (pitch 132), float4 writes ----
    {
        const int r0 = lane >> 2;
        const int cb = 2*(lane & 3);
        #pragma unroll
        for (int mb=0; mb<4; mb++) {
            #pragma unroll
            for (int j=0; j<4; j++) {
                int row = wm*64 + mb*16 + r0;
                int col = wn*32 + j*8 + cb;
                *reinterpret_cast<float2*>(&sm[row*132 + col])     = make_float2(acc[mb][j][0], acc[mb][j][1]);
                *reinterpret_cast<float2*>(&sm[(row+8)*132 + col]) = make_float2(acc[mb][j][2], acc[mb][j][3]);
            }
        }
    }
    __syncthreads();

    {
        const int row = tid >> 1;
        const int gm  = tileM + row;
        if (gm < M) {
            int b = 0, s = 0;
            if (OUTMODE == 1) { b = gm / SEQ; s = gm - b*SEQ; }
            #pragma unroll
            for (int f=0; f<16; f++) {
                int c  = (tid & 1)*64 + f*4;
                int gn = tileN + c;
                float4 v = *reinterpret_cast<const float4*>(&sm[row*132 + c]);
                v.x = (v.x + bias[gn  ]) * alpha;
                v.y = (v.y + bias[gn+1]) * alpha;
                v.z = (v.z + bias[gn+2]) * alpha;
                v.w = (v.w + bias[gn+3]) * alpha;
                if (EPI == 1) {
                    v.x = gelu_exact(v.x); v.y = gelu_exact(v.y);
                    v.z = gelu_exact(v.z); v.w = gelu_exact(v.w);
                }
                if (ROUND) {
                    v.x = tf32r(v.x); v.y = tf32r(v.y); v.z = tf32r(v.z); v.w = tf32r(v.w);
                }
                if (OUTMODE == 0) {
                    *reinterpret_cast<float4*>(&C[(size_t)gm*N + gn]) = v;
                } else {
                    int h = gn >> 6, dd = gn & 63;
                    size_t orow = (size_t)(b*NHEAD + h)*SEQ + s;
                    *reinterpret_cast<float4*>(&C[orow*HDIM + dd]) = v;
                }
            }
        }
    }
}

// =====================================================================
// Fused attention: one CTA per (bh, s-tile). 512 threads (16 warps).
// (R10 configuration, proven)
// =====================================================================
#define OFF_K   0
#define OFF_V   (SEQP*VL)
#define OFF_QO  (OFF_V + 64*KL)
#define OFF_S   (OFF_QO + 64*VL)
#define ATTN_SMEM_FLOATS (OFF_S + 64*KL)
#define ATTN_SMEM_BYTES  (ATTN_SMEM_FLOATS*4)

__launch_bounds__(512)
__global__ void attn_k(const float* __restrict__ q, const float* __restrict__ k,
                       const float* __restrict__ v, float* __restrict__ ctx)
{
    extern __shared__ float sm[];
    const uint32_t smBase = (uint32_t)__cvta_generic_to_shared(sm);
    float* Ksm = sm + OFF_K;
    float* Vsm = sm + OFF_V;
    float* QO  = sm + OFF_QO;
    float* Ssm = sm + OFF_S;

    const int bh   = blockIdx.x >> 2;
    const int tile = blockIdx.x & 3;
    const int s0   = tile * 64;
    const int valid = (SEQ - s0) < 64 ? (SEQ - s0) : 64;
    const int miMax = (valid + 15) >> 4;

    const int b  = bh / NHEAD;
    const int h  = bh - b*NHEAD;
    const int tid    = threadIdx.x;
    const int warpId = tid >> 5;
    const int lane   = tid & 31;

    const float* qb = q + (size_t)bh*SEQ*HDIM;
    const float* kb = k + (size_t)bh*SEQ*HDIM;
    const float* vb = v + (size_t)bh*SEQ*HDIM;

    const int aRowOff = (lane & 7) + ((lane >> 3) & 1) * 8;
    const int aKH     = (lane >> 4) * 4;
    const int bNOff   = (lane & 7) + (lane >> 4) * 8;
    const int bKH     = ((lane >> 3) & 1) * 4;
    const int r0 = lane >> 2;
    const int cb = 2*(lane & 3);

    for (int idx = tid; idx < SEQP*16; idx += 512) {
        int t = idx >> 4, f = idx & 15;
        float4 val = (t < SEQ) ? *reinterpret_cast<const float4*>(&kb[(size_t)t*HDIM + f*4])
                               : make_float4(0.f,0.f,0.f,0.f);
        *reinterpret_cast<float4*>(&Ksm[t*VL + f*4]) = val;
    }
    for (int idx = tid; idx < SEQP*HDIM; idx += 512) {
        int t = idx >> 6, d = idx & 63;
        Vsm[d*KL + t] = (t < SEQ) ? vb[(size_t)t*HDIM + d] : 0.f;
    }
    for (int idx = tid; idx < 64*16; idx += 512) {
        int r = idx >> 4, f = idx & 15;
        int s = s0 + r;
        float4 val = (s < SEQ) ? *reinterpret_cast<const float4*>(&qb[(size_t)s*HDIM + f*4])
                               : make_float4(0.f,0.f,0.f,0.f);
        *reinterpret_cast<float4*>(&QO[r*VL + f*4]) = val;
    }
    __syncthreads();

    for (int t = warpId; t < miMax*13; t += 16) {
        int mi = t / 13, ni = t - (t/13)*13;
        float c0[4] = {0.f,0.f,0.f,0.f}, c1[4] = {0.f,0.f,0.f,0.f};
        const uint32_t aAddr = smBase + (uint32_t)((OFF_QO + (mi*16 + aRowOff)*VL + aKH)*4);
        const uint32_t bAddr = smBase + (uint32_t)((OFF_K  + (ni*16 + bNOff)*VL + bKH)*4);
        #pragma unroll
        for (int ks=0; ks<8; ks++) {
            uint32_t a0,a1,a2,a3, b0,b1,b2,b3;
            ldsm4(aAddr + ks*32, a0,a1,a2,a3);
            ldsm4(bAddr + ks*32, b0,b1,b2,b3);
            mma_tf32(c0, a0,a1,a2,a3, b0,b1);
            mma_tf32(c1, a0,a1,a2,a3, b2,b3);
        }
        {
            int row = mi*16 + r0, col = ni*16 + cb;
            *reinterpret_cast<float2*>(&Ssm[row*KL + col])         = make_float2(c0[0], c0[1]);
            *reinterpret_cast<float2*>(&Ssm[(row+8)*KL + col])     = make_float2(c0[2], c0[3]);
            *reinterpret_cast<float2*>(&Ssm[row*KL + col + 8])     = make_float2(c1[0], c1[1]);
            *reinterpret_cast<float2*>(&Ssm[(row+8)*KL + col + 8]) = make_float2(c1[2], c1[3]);
        }
    }
    __syncthreads();

    for (int rr = 0; rr < miMax; rr++) {
        int r = rr*16 + warpId;
        float* rowp = &Ssm[r*KL];
        float x[7];
        float m = -1e30f;
        #pragma unroll
        for (int i=0;i<7;i++) {
            int c = lane + i*32;
            x[i] = (c < SEQ) ? rowp[c] : -1e30f;
            m = fmaxf(m, x[i]);
        }
        #pragma unroll
        for (int o=16;o;o>>=1) m = fmaxf(m, __shfl_xor_sync(0xffffffffu, m, o));
        float sum = 0.f;
        #pragma unroll
        for (int i=0;i<7;i++) { x[i] = __expf(x[i] - m); sum += x[i]; }
        #pragma unroll
        for (int o=16;o;o>>=1) sum += __shfl_xor_sync(0xffffffffu, sum, o);
        float inv = 1.f / sum;
        #pragma unroll
        for (int i=0;i<7;i++) {
            int c = lane + i*32;
            if (c < SEQ)       rowp[c] = tf32r(x[i]*inv);
            else if (c < SEQP) rowp[c] = 0.f;
        }
    }
    __syncthreads();

    if (warpId < miMax*4) {
        int mi = warpId >> 2, ni = warpId & 3;
        float c0[4] = {0.f,0.f,0.f,0.f}, c1[4] = {0.f,0.f,0.f,0.f};
        const uint32_t aAddr = smBase + (uint32_t)((OFF_S + (mi*16 + aRowOff)*KL + aKH)*4);
        const uint32_t bAddr = smBase + (uint32_t)((OFF_V + (ni*16 + bNOff)*KL + bKH)*4);
        #pragma unroll
        for (int ks=0; ks<26; ks++) {
            uint32_t a0,a1,a2,a3, b0,b1,b2,b3;
            ldsm4(aAddr + ks*32, a0,a1,a2,a3);
            ldsm4(bAddr + ks*32, b0,b1,b2,b3);
            mma_tf32(c0, a0,a1,a2,a3, b0,b1);
            mma_tf32(c1, a0,a1,a2,a3, b2,b3);
        }
        {
            int row = mi*16 + r0, col = ni*16 + cb;
            *reinterpret_cast<float2*>(&QO[row*VL + col])         = make_float2(c0[0], c0[1]);
            *reinterpret_cast<float2*>(&QO[(row+8)*VL + col])     = make_float2(c0[2], c0[3]);
            *reinterpret_cast<float2*>(&QO[row*VL + col + 8])     = make_float2(c1[0], c1[1]);
            *reinterpret_cast<float2*>(&QO[(row+8)*VL + col + 8]) = make_float2(c1[2], c1[3]);
        }
    }
    __syncthreads();

    for (int idx = tid; idx < valid*16; idx += 512) {
        int r = idx >> 4, f = idx & 15;
        int s = s0 + r;
        float4 val = *reinterpret_cast<const float4*>(&QO[r*VL + f*4]);
        val.x=tf32r(val.x); val.y=tf32r(val.y); val.z=tf32r(val.z); val.w=tf32r(val.w);
        *reinterpret_cast<float4*>(&ctx[((size_t)(b*SEQ + s))*DIM + h*HDIM + f*4]) = val;
    }
}

// ---------------- residual + LayerNorm (float4 vectorized) ----------------
__launch_bounds__(192)
__global__ void add_ln_k(const float* __restrict__ x, const float* __restrict__ y,
                         const float* __restrict__ g, const float* __restrict__ be,
                         float* __restrict__ out, float* __restrict__ outR)
{
    const int r = blockIdx.x;
    const int t = threadIdx.x;
    const float4 yv = *reinterpret_cast<const float4*>(&y[(size_t)r*DIM + t*4]);

    float s  = yv.x + yv.y + yv.z + yv.w;
    float sq = yv.x*yv.x + yv.y*yv.y + yv.z*yv.z + yv.w*yv.w;

    __shared__ float red[12];
    #pragma unroll
    for (int o=16;o;o>>=1) { s += __shfl_xor_sync(0xffffffffu, s, o); sq += __shfl_xor_sync(0xffffffffu, sq, o); }
    int w = t >> 5, lane = t & 31;
    if (lane == 0) { red[w] = s; red[w+6] = sq; }
    __syncthreads();
    if (t < 32) {
        s  = (lane < 6) ? red[lane]     : 0.f;
        sq = (lane < 6) ? red[lane + 6] : 0.f;
        #pragma unroll
        for (int o=4;o;o>>=1) { s += __shfl_xor_sync(0xffffffffu, s, o); sq += __shfl_xor_sync(0xffffffffu, sq, o); }
        if (lane == 0) { red[0] = s; red[1] = sq; }
    }
    __syncthreads();
    const float mu   = red[0] * (1.f/DIM);
    const float var  = red[1] * (1.f/DIM) - mu*mu;
    const float rstd = rsqrtf(var + LN_EPS);

    const float4 xv = *reinterpret_cast<const float4*>(&x[(size_t)r*DIM + t*4]);
    const float4 gv = *reinterpret_cast<const float4*>(&g[t*4]);
    const float4 bv = *reinterpret_cast<const float4*>(&be[t*4]);
    float4 o;
    o.x = xv.x + (yv.x - mu)*rstd*gv.x + bv.x;
    o.y = xv.y + (yv.y - mu)*rstd*gv.y + bv.y;
    o.z = xv.z + (yv.z - mu)*rstd*gv.z + bv.z;
    o.w = xv.w + (yv.w - mu)*rstd*gv.w + bv.w;
    *reinterpret_cast<float4*>(&out[(size_t)r*DIM + t*4]) = o;
    if (outR) {
        float4 orr;
        orr.x = tf32r(o.x); orr.y = tf32r(o.y); orr.z = tf32r(o.z); orr.w = tf32r(o.w);
        *reinterpret_cast<float4*>(&outR[(size_t)r*DIM + t*4]) = orr;
    }
}

// ---------------- launch ----------------
extern "C" void kernel_launch(void* const* d_in, const int* in_sizes, int n_in,
                              void* d_out, int out_size)
{
    const float* x   = (const float*)d_in[0];
    const float* Wq  = (const float*)d_in[1];
    const float* bq  = (const float*)d_in[2];
    const float* Wk  = (const float*)d_in[3];
    const float* bk  = (const float*)d_in[4];
    const float* Wv  = (const float*)d_in[5];
    const float* bv  = (const float*)d_in[6];
    const float* Wo  = (const float*)d_in[7];
    const float* bo  = (const float*)d_in[8];
    const float* W1  = (const float*)d_in[9];
    const float* b1  = (const float*)d_in[10];
    const float* W2  = (const float*)d_in[11];
    const float* b2  = (const float*)d_in[12];
    const float* g1  = (const float*)d_in[13];
    const float* be1 = (const float*)d_in[14];
    const float* g2  = (const float*)d_in[15];
    const float* be2 = (const float*)d_in[16];
    float* out = (float*)d_out;

    float *q,*k,*v,*ctx,*ao,*x1,*x1r,*xr,*hh,*mlp;
    float *wqT,*wkT,*wvT,*woT,*w1T,*w2T;
    cudaGetSymbolAddress((void**)&q,   g_q);
    cudaGetSymbolAddress((void**)&k,   g_k);
    cudaGetSymbolAddress((void**)&v,   g_v);
    cudaGetSymbolAddress((void**)&ctx, g_ctx);
    cudaGetSymbolAddress((void**)&ao,  g_ao);
    cudaGetSymbolAddress((void**)&x1,  g_x1);
    cudaGetSymbolAddress((void**)&x1r, g_x1r);
    cudaGetSymbolAddress((void**)&xr,  g_xr);
    cudaGetSymbolAddress((void**)&hh,  g_h);
    cudaGetSymbolAddress((void**)&mlp, g_mlp);
    cudaGetSymbolAddress((void**)&wqT, g_wqT);
    cudaGetSymbolAddress((void**)&wkT, g_wkT);
    cudaGetSymbolAddress((void**)&wvT, g_wvT);
    cudaGetSymbolAddress((void**)&woT, g_woT);
    cudaGetSymbolAddress((void**)&w1T, g_w1T);
    cudaGetSymbolAddress((void**)&w2T, g_w2T);

    cudaFuncSetAttribute(tgemm_k<1,0,1>, cudaFuncAttributeMaxDynamicSharedMemorySize, GEMM_SMEM_BYTES);
    cudaFuncSetAttribute(tgemm_k<0,0,0>, cudaFuncAttributeMaxDynamicSharedMemorySize, GEMM_SMEM_BYTES);
    cudaFuncSetAttribute(tgemm_k<0,1,1>, cudaFuncAttributeMaxDynamicSharedMemorySize, GEMM_SMEM_BYTES);
    cudaFuncSetAttribute(attn_k,         cudaFuncAttributeMaxDynamicSharedMemorySize, ATTN_SMEM_BYTES);

    // --- pre-pass: exactly 4 launches so the QKV GEMM is the 5th (ncu -s 5 target) ---
    {
        int n = TOK*DIM/4;
        round_k<<<(n+255)/256, 256>>>(x, xr, n);                       // launch 1
        dim3 tg(DIM/32, DIM/32, 2);
        troundT2_k<<<tg, 256>>>(Wq, wqT, Wk, wkT, DIM, DIM);           // launch 2
        troundT2_k<<<tg, 256>>>(Wv, wvT, Wo, woT, DIM, DIM);           // launch 3
        dim3 tg12(HID/32, HID/32, 2);                                  // superset grid; early-exit
        troundT12_k<<<tg12, 256>>>(W1, w1T, W2, w2T);                  // launch 4
    }

    const int mtiles = (TOK + 127)/128;   // 99

    // --- fused QKV projection (launch 5) ---
    {
        dim3 grid(DIM/128, mtiles, 3);
        tgemm_k<1,0,1><<<grid, 256, GEMM_SMEM_BYTES>>>(xr, wqT, wkT, wvT, bq, bk, bv,
                                                       q, k, v, TOK, DIM, DIM,
                                                       0.125f, 1.0f, 1.0f);
    }

    // --- fused attention -> ctx (rounded) ---
    attn_k<<<BH*4, 512, ATTN_SMEM_BYTES>>>(q, k, v, ctx);

    // --- attn_out = ctx @ Wo + bo ---
    {
        dim3 grid(DIM/128, mtiles, 1);
        tgemm_k<0,0,0><<<grid, 256, GEMM_SMEM_BYTES>>>(ctx, woT, woT, woT, bo, bo, bo,
                                                       ao, ao, ao, TOK, DIM, DIM,
                                                       1.0f, 1.0f, 1.0f);
    }

    // --- x1 = x + LN(attn_out); rounded copy for MLP1 ---
    add_ln_k<<<TOK, 192>>>(x, ao, g1, be1, x1, x1r);

    // --- h = gelu(x1 @ W1 + b1) (rounded) ---
    {
        dim3 grid(HID/128, mtiles, 1);
        tgemm_k<0,1,1><<<grid, 256, GEMM_SMEM_BYTES>>>(x1r, w1T, w1T, w1T, b1, b1, b1,
                                                       hh, hh, hh, TOK, HID, DIM,
                                                       1.0f, 1.0f, 1.0f);
    }

    // --- mlp = h @ W2 + b2 ---
    {
        dim3 grid(DIM/128, mtiles, 1);
        tgemm_k<0,0,0><<<grid, 256, GEMM_SMEM_BYTES>>>(hh, w2T, w2T, w2T, b2, b2, b2,
                                                       mlp, mlp, mlp, TOK, DIM, HID,
                                                       1.0f, 1.0f, 1.0f);
    }

    // --- out = x1 + LN(mlp) ---
    add_ln_k<<<TOK, 192>>>(x1, mlp, g2, be2, out, nullptr);
}

// round 13
// speedup vs baseline: 2.0144x; 1.4547x over previous
#include <cuda_runtime.h>
#include <cuda_fp16.h>
#include <math.h>
#include <stdint.h>

// ---------------- problem constants ----------------
#define BATCH   64
#define SEQ     197
#define TOK     (BATCH*SEQ)      // 12608
#define DIM     768
#define NHEAD   12
#define HDIM    64
#define HID     3072
#define BH      (BATCH*NHEAD)    // 768
#define LN_EPS  1e-6f

// ---------------- scratch (device globals) ----------------
__device__ __half g_xh  [(long)TOK*DIM];
__device__ __half g_qh  [(long)BH*SEQ*HDIM];
__device__ __half g_kh  [(long)BH*SEQ*HDIM];
__device__ __half g_vh  [(long)BH*SEQ*HDIM];
__device__ __half g_ctxh[(long)TOK*DIM];
__device__ __half g_x1h [(long)TOK*DIM];
__device__ __half g_hh  [(long)TOK*HID];
__device__ float  g_ao  [(long)TOK*DIM];
__device__ float  g_x1  [(long)TOK*DIM];
__device__ float  g_mlp [(long)TOK*DIM];
// transposed + fp16-rounded weights: [N][K]
__device__ __half g_wqT[DIM*DIM];
__device__ __half g_wkT[DIM*DIM];
__device__ __half g_wvT[DIM*DIM];
__device__ __half g_woT[DIM*DIM];
__device__ __half g_w1T[(long)HID*DIM];
__device__ __half g_w2T[(long)DIM*HID];

__device__ __forceinline__ float gelu_exact(float v) {
    return 0.5f * v * (1.f + erff(v * 0.70710678118654752f));
}
__device__ __forceinline__ void cpa16(uint32_t dst, const void* src) {
    asm volatile("cp.async.cg.shared.global [%0], [%1], 16;" :: "r"(dst), "l"(src) : "memory");
}
__device__ __forceinline__ void ldsm4(uint32_t addr, uint32_t& r0, uint32_t& r1,
                                      uint32_t& r2, uint32_t& r3) {
    asm volatile("ldmatrix.sync.aligned.m8n8.x4.shared.b16 {%0,%1,%2,%3}, [%4];"
                 : "=r"(r0), "=r"(r1), "=r"(r2), "=r"(r3) : "r"(addr));
}
__device__ __forceinline__ void mma_f16(float* c, uint32_t a0, uint32_t a1,
                                        uint32_t a2, uint32_t a3,
                                        uint32_t b0, uint32_t b1) {
    asm volatile("mma.sync.aligned.m16n8k16.row.col.f32.f16.f16.f32 "
                 "{%0,%1,%2,%3}, {%4,%5,%6,%7}, {%8,%9}, {%0,%1,%2,%3};"
                 : "+f"(c[0]), "+f"(c[1]), "+f"(c[2]), "+f"(c[3])
                 : "r"(a0), "r"(a1), "r"(a2), "r"(a3), "r"(b0), "r"(b1));
}
__device__ __forceinline__ uint4 pack8h(float v0, float v1, float v2, float v3,
                                        float v4, float v5, float v6, float v7) {
    union { __half2 h[4]; uint4 u; } pk;
    pk.h[0] = __floats2half2_rn(v0, v1);
    pk.h[1] = __floats2half2_rn(v2, v3);
    pk.h[2] = __floats2half2_rn(v4, v5);
    pk.h[3] = __floats2half2_rn(v6, v7);
    return pk.u;
}

// ---------------- float -> fp16 rounding kernel ----------------
__global__ void roundh_k(const float* __restrict__ src, __half* __restrict__ dst, int n4)
{
    int i = blockIdx.x*blockDim.x + threadIdx.x;
    if (i < n4) {
        float4 v = reinterpret_cast<const float4*>(src)[i];
        union { __half2 h[2]; uint2 u; } pk;
        pk.h[0] = __floats2half2_rn(v.x, v.y);
        pk.h[1] = __floats2half2_rn(v.z, v.w);
        reinterpret_cast<uint2*>(dst)[i] = pk.u;
    }
}

// ---------------- transpose + fp16-round: src[K][N] -> dst[N][K] ----------------
__global__ void troundT2_k(const float* __restrict__ s0, __half* __restrict__ d0,
                           const float* __restrict__ s1, __half* __restrict__ d1,
                           int K, int N)
{
    const float* src = blockIdx.z ? s1 : s0;
    __half*      dst = blockIdx.z ? d1 : d0;
    __shared__ float t[32][33];
    const int n0 = blockIdx.x*32, k0 = blockIdx.y*32;
    const int tx = threadIdx.x & 31, tg = threadIdx.x >> 5;
    #pragma unroll
    for (int i=0;i<4;i++) {
        int r = tg + i*8;
        t[r][tx] = src[(size_t)(k0+r)*N + n0 + tx];
    }
    __syncthreads();
    #pragma unroll
    for (int i=0;i<4;i++) {
        int r = tg + i*8;
        dst[(size_t)(n0+r)*K + k0 + tx] = __float2half_rn(t[tx][r]);
    }
}

__global__ void troundT12_k(const float* __restrict__ s0, __half* __restrict__ d0,
                            const float* __restrict__ s1, __half* __restrict__ d1)
{
    int K, N;
    const float* src;
    __half* dst;
    if (blockIdx.z == 0) {
        if (blockIdx.x >= HID/32 || blockIdx.y >= DIM/32) return;
        src = s0; dst = d0; K = DIM; N = HID;
    } else {
        if (blockIdx.x >= DIM/32 || blockIdx.y >= HID/32) return;
        src = s1; dst = d1; K = HID; N = DIM;
    }
    __shared__ float t[32][33];
    const int n0 = blockIdx.x*32, k0 = blockIdx.y*32;
    const int tx = threadIdx.x & 31, tg = threadIdx.x >> 5;
    #pragma unroll
    for (int i=0;i<4;i++) {
        int r = tg + i*8;
        t[r][tx] = src[(size_t)(k0+r)*N + n0 + tx];
    }
    __syncthreads();
    #pragma unroll
    for (int i=0;i<4;i++) {
        int r = tg + i*8;
        dst[(size_t)(n0+r)*K + k0 + tx] = __float2half_rn(t[tx][r]);
    }
}

// =====================================================================
// FP16 GEMM via ldmatrix + mma.m16n8k16 (fp32 accumulate).
// 128x128x32 tiles, 8 warps (64x32 warp tiles), 2 CTAs/SM.
// 3-stage cp.async pipeline, single __syncthreads per k-step.
// Smem-staged epilogue with coalesced stores.
// OUTMODE: 0 plain [M,N]; 1 head-split. EPI: 1 GELU.
// OUTHALF: 1 -> fp16-rounded half output, 0 -> float output.
// =====================================================================
#define APITCH 40                             // halves per row (32 + 8 pad)
#define STAGE_BYTES (128*APITCH*2*2)          // A+B = 20480
#define GEMM_SMEM_BYTES (128*132*4)           // 67584 (epilogue dominates; 3*20480=61440 fits)

template<int OUTMODE,int EPI,int OUTHALF>
__launch_bounds__(256, 2)
__global__ void tgemm_k(const __half* __restrict__ A,
                        const __half* __restrict__ B0, const __half* __restrict__ B1, const __half* __restrict__ B2,
                        const float* __restrict__ c0, const float* __restrict__ c1, const float* __restrict__ c2,
                        void* __restrict__ D0, void* __restrict__ D1, void* __restrict__ D2,
                        int M, int N, int K, float a0, float a1, float a2)
{
    extern __shared__ char smc[];
    float* smf = reinterpret_cast<float*>(smc);
    const uint32_t smBase = (uint32_t)__cvta_generic_to_shared(smc);

    const int z = blockIdx.z;
    const __half* Bt  = (z==0) ? B0 : (z==1) ? B1 : B2;
    const float* bias = (z==0) ? c0 : (z==1) ? c1 : c2;
    void*        Dv   = (z==0) ? D0 : (z==1) ? D1 : D2;
    const float alpha = (z==0) ? a0 : (z==1) ? a1 : a2;

    const int tileM = blockIdx.y * 128;
    const int tileN = blockIdx.x * 128;
    const int tid   = threadIdx.x;
    const int warpId= tid >> 5;
    const int lane  = tid & 31;
    const int wm    = warpId >> 2;      // 0..1
    const int wn    = warpId & 3;       // 0..3

    // cp.async mapping: 16B = 8 halves; 4 threads per 32-half row
    const int ldRow = tid >> 2;         // 0..63
    const int ldCol = (tid & 3) << 3;   // 0,8,16,24 halves

    const __half* aPtr[2];
    #pragma unroll
    for (int t=0;t<2;t++) {
        int gm = tileM + t*64 + ldRow;
        if (gm > M-1) gm = M-1;
        aPtr[t] = A + (size_t)gm*K + ldCol;
    }
    const __half* bPtr[2];
    #pragma unroll
    for (int t=0;t<2;t++)
        bPtr[t] = Bt + (size_t)(tileN + t*64 + ldRow)*K + ldCol;

    // ldmatrix lane constants (std x4 map; same for A and B tiles)
    const int rowOff = (lane & 7) + ((lane >> 3) & 1) * 8;
    const int kOff   = (lane >> 4) * 8;   // halves (16B)

    const uint32_t aAddr0 = smBase + (uint32_t)(((wm*64 + rowOff)*APITCH + kOff) * 2);
    const uint32_t bAddr0 = smBase + (uint32_t)((128*APITCH + (wn*32 + rowOff)*APITCH + kOff) * 2);

    float acc[4][4][4];
    #pragma unroll
    for (int i=0;i<4;i++)
        #pragma unroll
        for (int j=0;j<4;j++)
            #pragma unroll
            for (int t=0;t<4;t++) acc[i][j][t] = 0.f;

    auto loadStage = [&](int k0, int st) {
        const uint32_t ab = smBase + (uint32_t)st*STAGE_BYTES;
        const uint32_t bb = ab + 128*APITCH*2;
        #pragma unroll
        for (int t=0;t<2;t++)
            cpa16(ab + (uint32_t)(((t*64 + ldRow)*APITCH + ldCol)*2), aPtr[t] + k0);
        #pragma unroll
        for (int t=0;t<2;t++)
            cpa16(bb + (uint32_t)(((t*64 + ldRow)*APITCH + ldCol)*2), bPtr[t] + k0);
        asm volatile("cp.async.commit_group;" ::: "memory");
    };

    const int NS = K >> 5;
    loadStage(0, 0);
    if (NS > 1) loadStage(32, 1);

    int st = 0;
    for (int s = 0; s < NS; s++) {
        if (s + 1 < NS) asm volatile("cp.async.wait_group 1;" ::: "memory");
        else            asm volatile("cp.async.wait_group 0;" ::: "memory");
        __syncthreads();

        if (s + 2 < NS) {
            int nst = st + 2; if (nst >= 3) nst -= 3;
            loadStage((s+2) << 5, nst);
        }

        const uint32_t aS = aAddr0 + (uint32_t)st*STAGE_BYTES;
        const uint32_t bS = bAddr0 + (uint32_t)st*STAGE_BYTES;
        #pragma unroll
        for (int ks=0; ks<2; ks++) {
            uint32_t a[4][4], b[2][4];
            #pragma unroll
            for (int mb=0; mb<4; mb++)
                ldsm4(aS + (uint32_t)(mb*16*APITCH*2 + ks*32), a[mb][0], a[mb][1], a[mb][2], a[mb][3]);
            #pragma unroll
            for (int nb=0; nb<2; nb++)
                ldsm4(bS + (uint32_t)(nb*16*APITCH*2 + ks*32), b[nb][0], b[nb][1], b[nb][2], b[nb][3]);
            #pragma unroll
            for (int mb=0; mb<4; mb++)
                #pragma unroll
                for (int j=0; j<4; j++)
                    mma_f16(acc[mb][j], a[mb][0], a[mb][1], a[mb][2], a[mb][3],
                            b[j>>1][j&1], b[j>>1][(j&1)+2]);
        }
        if (++st == 3) st = 0;
    }
    __syncthreads();

    // ---- epilogue: stage 128x128 fp32 tile in smem (pitch 132) ----
    {
        const int r0 = lane >> 2;
        const int cb = 2*(lane & 3);
        #pragma unroll
        for (int mb=0; mb<4; mb++) {
            #pragma unroll
            for (int j=0; j<4; j++) {
                int row = wm*64 + mb*16 + r0;
                int col = wn*32 + j*8 + cb;
                *reinterpret_cast<float2*>(&smf[row*132 + col])     = make_float2(acc[mb][j][0], acc[mb][j][1]);
                *reinterpret_cast<float2*>(&smf[(row+8)*132 + col]) = make_float2(acc[mb][j][2], acc[mb][j][3]);
            }
        }
    }
    __syncthreads();

    {
        const int row = tid >> 1;
        const int gm  = tileM + row;
        if (gm < M) {
            int b = 0, s = 0;
            if (OUTMODE == 1) { b = gm / SEQ; s = gm - b*SEQ; }
            if (OUTHALF == 0) {
                float* C = reinterpret_cast<float*>(Dv);
                #pragma unroll
                for (int f=0; f<16; f++) {
                    int c  = (tid & 1)*64 + f*4;
                    int gn = tileN + c;
                    float4 v = *reinterpret_cast<const float4*>(&smf[row*132 + c]);
                    v.x = (v.x + bias[gn  ]) * alpha;
                    v.y = (v.y + bias[gn+1]) * alpha;
                    v.z = (v.z + bias[gn+2]) * alpha;
                    v.w = (v.w + bias[gn+3]) * alpha;
                    if (EPI == 1) {
                        v.x = gelu_exact(v.x); v.y = gelu_exact(v.y);
                        v.z = gelu_exact(v.z); v.w = gelu_exact(v.w);
                    }
                    *reinterpret_cast<float4*>(&C[(size_t)gm*N + gn]) = v;
                }
            } else {
                __half* C = reinterpret_cast<__half*>(Dv);
                #pragma unroll
                for (int f=0; f<8; f++) {
                    int c  = (tid & 1)*64 + f*8;
                    int gn = tileN + c;
                    float4 v0 = *reinterpret_cast<const float4*>(&smf[row*132 + c]);
                    float4 v1 = *reinterpret_cast<const float4*>(&smf[row*132 + c + 4]);
                    float w0 = (v0.x + bias[gn  ]) * alpha;
                    float w1 = (v0.y + bias[gn+1]) * alpha;
                    float w2 = (v0.z + bias[gn+2]) * alpha;
                    float w3 = (v0.w + bias[gn+3]) * alpha;
                    float w4 = (v1.x + bias[gn+4]) * alpha;
                    float w5 = (v1.y + bias[gn+5]) * alpha;
                    float w6 = (v1.z + bias[gn+6]) * alpha;
                    float w7 = (v1.w + bias[gn+7]) * alpha;
                    if (EPI == 1) {
                        w0 = gelu_exact(w0); w1 = gelu_exact(w1);
                        w2 = gelu_exact(w2); w3 = gelu_exact(w3);
                        w4 = gelu_exact(w4); w5 = gelu_exact(w5);
                        w6 = gelu_exact(w6); w7 = gelu_exact(w7);
                    }
                    uint4 u = pack8h(w0,w1,w2,w3,w4,w5,w6,w7);
                    if (OUTMODE == 0) {
                        *reinterpret_cast<uint4*>(&C[(size_t)gm*N + gn]) = u;
                    } else {
                        int h = gn >> 6, dd = gn & 63;
                        size_t orow = (size_t)(b*NHEAD + h)*SEQ + s;
                        *reinterpret_cast<uint4*>(&C[orow*HDIM + dd]) = u;
                    }
                }
            }
        }
    }
}

// =====================================================================
// Fused attention, fp16 operands. One CTA per (bh, s-tile), 512 threads.
// Kh [t][72h] d-contig; Vh = V^T [d][216h] t-contig; Qh/O [64][72h];
// Sf fp32 [64][212]; Ph [64][216h].
// =====================================================================
#define AT_KP 72
#define AT_TP 216
#define AT_SP 212
#define OFFB_K 0
#define OFFB_V (208*AT_KP*2)                  // 29952
#define OFFB_Q (OFFB_V + 64*AT_TP*2)          // 57600
#define OFFB_S (OFFB_Q + 64*AT_KP*2)          // 66816
#define OFFB_P (OFFB_S + 64*AT_SP*4)          // 121088
#define ATTN_SMEM_BYTES (OFFB_P + 64*AT_TP*2) // 148736

__launch_bounds__(512)
__global__ void attn_k(const __half* __restrict__ q, const __half* __restrict__ k,
                       const __half* __restrict__ v, __half* __restrict__ ctx)
{
    extern __shared__ char smc[];
    const uint32_t smBase = (uint32_t)__cvta_generic_to_shared(smc);
    __half* Kh = reinterpret_cast<__half*>(smc + OFFB_K);
    __half* Vh = reinterpret_cast<__half*>(smc + OFFB_V);
    __half* Qh = reinterpret_cast<__half*>(smc + OFFB_Q);
    float*  Sf = reinterpret_cast<float*>(smc + OFFB_S);
    __half* Ph = reinterpret_cast<__half*>(smc + OFFB_P);

    const int bh   = blockIdx.x >> 2;
    const int tile = blockIdx.x & 3;
    const int s0   = tile * 64;
    const int valid = (SEQ - s0) < 64 ? (SEQ - s0) : 64;
    const int miMax = (valid + 15) >> 4;

    const int b  = bh / NHEAD;
    const int h  = bh - b*NHEAD;
    const int tid    = threadIdx.x;
    const int warpId = tid >> 5;
    const int lane   = tid & 31;

    const __half* qb = q + (size_t)bh*SEQ*HDIM;
    const __half* kb = k + (size_t)bh*SEQ*HDIM;
    const __half* vb = v + (size_t)bh*SEQ*HDIM;

    const int rowOff = (lane & 7) + ((lane >> 3) & 1) * 8;
    const int kOff   = (lane >> 4) * 8;
    const int r0 = lane >> 2;
    const int cb = 2*(lane & 3);

    const uint4 zero4 = make_uint4(0u,0u,0u,0u);

    // K [t][d] direct
    for (int idx = tid; idx < 208*8; idx += 512) {
        int t = idx >> 3, f = idx & 7;
        uint4 val = (t < SEQ) ? *reinterpret_cast<const uint4*>(kb + (size_t)t*HDIM + f*8) : zero4;
        *reinterpret_cast<uint4*>(Kh + t*AT_KP + f*8) = val;
    }
    // V^T [d][t]
    for (int idx = tid; idx < 208*64; idx += 512) {
        int t = idx >> 6, d = idx & 63;
        Vh[d*AT_TP + t] = (t < SEQ) ? vb[(size_t)t*HDIM + d] : __float2half(0.f);
    }
    // Q tile
    for (int idx = tid; idx < 64*8; idx += 512) {
        int r = idx >> 3, f = idx & 7;
        int s = s0 + r;
        uint4 val = (s < SEQ) ? *reinterpret_cast<const uint4*>(qb + (size_t)s*HDIM + f*8) : zero4;
        *reinterpret_cast<uint4*>(Qh + r*AT_KP + f*8) = val;
    }
    __syncthreads();

    // ---- scores: miMax x 13 warp tiles ----
    for (int t = warpId; t < miMax*13; t += 16) {
        int mi = t / 13, ni = t - (t/13)*13;
        float c0[4] = {0.f,0.f,0.f,0.f}, c1[4] = {0.f,0.f,0.f,0.f};
        const uint32_t aAddr = smBase + OFFB_Q + (uint32_t)(((mi*16 + rowOff)*AT_KP + kOff)*2);
        const uint32_t bAddr = smBase + OFFB_K + (uint32_t)(((ni*16 + rowOff)*AT_KP + kOff)*2);
        #pragma unroll
        for (int ks=0; ks<4; ks++) {
            uint32_t a0,a1,a2,a3, b0,b1,b2,b3;
            ldsm4(aAddr + ks*32, a0,a1,a2,a3);
            ldsm4(bAddr + ks*32, b0,b1,b2,b3);
            mma_f16(c0, a0,a1,a2,a3, b0,b2);
            mma_f16(c1, a0,a1,a2,a3, b1,b3);
        }
        {
            int row = mi*16 + r0, col = ni*16 + cb;
            *reinterpret_cast<float2*>(&Sf[row*AT_SP + col])         = make_float2(c0[0], c0[1]);
            *reinterpret_cast<float2*>(&Sf[(row+8)*AT_SP + col])     = make_float2(c0[2], c0[3]);
            *reinterpret_cast<float2*>(&Sf[row*AT_SP + col + 8])     = make_float2(c1[0], c1[1]);
            *reinterpret_cast<float2*>(&Sf[(row+8)*AT_SP + col + 8]) = make_float2(c1[2], c1[3]);
        }
    }
    __syncthreads();

    // ---- softmax: fp32 in Sf, fp16 out to Ph ----
    for (int rr = 0; rr < miMax; rr++) {
        int r = rr*16 + warpId;
        float* rowp = &Sf[r*AT_SP];
        float x[7];
        float m = -1e30f;
        #pragma unroll
        for (int i=0;i<7;i++) {
            int c = lane + i*32;
            x[i] = (c < SEQ) ? rowp[c] : -1e30f;
            m = fmaxf(m, x[i]);
        }
        #pragma unroll
        for (int o=16;o;o>>=1) m = fmaxf(m, __shfl_xor_sync(0xffffffffu, m, o));
        float sum = 0.f;
        #pragma unroll
        for (int i=0;i<7;i++) { x[i] = __expf(x[i] - m); sum += x[i]; }
        #pragma unroll
        for (int o=16;o;o>>=1) sum += __shfl_xor_sync(0xffffffffu, sum, o);
        float inv = 1.f / sum;
        #pragma unroll
        for (int i=0;i<7;i++) {
            int c = lane + i*32;
            if (c < SEQ)      Ph[r*AT_TP + c] = __float2half_rn(x[i]*inv);
            else if (c < 208) Ph[r*AT_TP + c] = __float2half(0.f);
        }
    }
    __syncthreads();

    // ---- O = P @ V^T-layout: miMax*4 warp tiles ----
    if (warpId < miMax*4) {
        int mi = warpId >> 2, ni = warpId & 3;
        float c0[4] = {0.f,0.f,0.f,0.f}, c1[4] = {0.f,0.f,0.f,0.f};
        const uint32_t aAddr = smBase + OFFB_P + (uint32_t)(((mi*16 + rowOff)*AT_TP + kOff)*2);
        const uint32_t bAddr = smBase + OFFB_V + (uint32_t)(((ni*16 + rowOff)*AT_TP + kOff)*2);
        #pragma unroll
        for (int ks=0; ks<13; ks++) {
            uint32_t a0,a1,a2,a3, b0,b1,b2,b3;
            ldsm4(aAddr + ks*32, a0,a1,a2,a3);
            ldsm4(bAddr + ks*32, b0,b1,b2,b3);
            mma_f16(c0, a0,a1,a2,a3, b0,b2);
            mma_f16(c1, a0,a1,a2,a3, b1,b3);
        }
        {
            int row = mi*16 + r0, col = ni*16 + cb;
            *reinterpret_cast<__half2*>(Qh + row*AT_KP + col)       = __floats2half2_rn(c0[0], c0[1]);
            *reinterpret_cast<__half2*>(Qh + (row+8)*AT_KP + col)   = __floats2half2_rn(c0[2], c0[3]);
            *reinterpret_cast<__half2*>(Qh + row*AT_KP + col+8)     = __floats2half2_rn(c1[0], c1[1]);
            *reinterpret_cast<__half2*>(Qh + (row+8)*AT_KP + col+8) = __floats2half2_rn(c1[2], c1[3]);
        }
    }
    __syncthreads();

    // ---- write ctx rows (half) ----
    for (int idx = tid; idx < valid*8; idx += 512) {
        int r = idx >> 3, f = idx & 7;
        int s = s0 + r;
        uint4 val = *reinterpret_cast<const uint4*>(Qh + r*AT_KP + f*8);
        *reinterpret_cast<uint4*>(ctx + ((size_t)(b*SEQ + s))*DIM + h*HDIM + f*8) = val;
    }
}

// ---------------- residual + LayerNorm (float4; optional half copy) ----------------
__launch_bounds__(192)
__global__ void add_ln_k(const float* __restrict__ x, const float* __restrict__ y,
                         const float* __restrict__ g, const float* __restrict__ be,
                         float* __restrict__ out, __half* __restrict__ outR)
{
    const int r = blockIdx.x;
    const int t = threadIdx.x;
    const float4 yv = *reinterpret_cast<const float4*>(&y[(size_t)r*DIM + t*4]);

    float s  = yv.x + yv.y + yv.z + yv.w;
    float sq = yv.x*yv.x + yv.y*yv.y + yv.z*yv.z + yv.w*yv.w;

    __shared__ float red[12];
    #pragma unroll
    for (int o=16;o;o>>=1) { s += __shfl_xor_sync(0xffffffffu, s, o); sq += __shfl_xor_sync(0xffffffffu, sq, o); }
    int w = t >> 5, lane = t & 31;
    if (lane == 0) { red[w] = s; red[w+6] = sq; }
    __syncthreads();
    if (t < 32) {
        s  = (lane < 6) ? red[lane]     : 0.f;
        sq = (lane < 6) ? red[lane + 6] : 0.f;
        #pragma unroll
        for (int o=4;o;o>>=1) { s += __shfl_xor_sync(0xffffffffu, s, o); sq += __shfl_xor_sync(0xffffffffu, sq, o); }
        if (lane == 0) { red[0] = s; red[1] = sq; }
    }
    __syncthreads();
    const float mu   = red[0] * (1.f/DIM);
    const float var  = red[1] * (1.f/DIM) - mu*mu;
    const float rstd = rsqrtf(var + LN_EPS);

    const float4 xv = *reinterpret_cast<const float4*>(&x[(size_t)r*DIM + t*4]);
    const float4 gv = *reinterpret_cast<const float4*>(&g[t*4]);
    const float4 bv = *reinterpret_cast<const float4*>(&be[t*4]);
    float4 o;
    o.x = xv.x + (yv.x - mu)*rstd*gv.x + bv.x;
    o.y = xv.y + (yv.y - mu)*rstd*gv.y + bv.y;
    o.z = xv.z + (yv.z - mu)*rstd*gv.z + bv.z;
    o.w = xv.w + (yv.w - mu)*rstd*gv.w + bv.w;
    *reinterpret_cast<float4*>(&out[(size_t)r*DIM + t*4]) = o;
    if (outR) {
        union { __half2 h[2]; uint2 u; } pk;
        pk.h[0] = __floats2half2_rn(o.x, o.y);
        pk.h[1] = __floats2half2_rn(o.z, o.w);
        *reinterpret_cast<uint2*>(outR + (size_t)r*DIM + t*4) = pk.u;
    }
}

// ---------------- launch ----------------
extern "C" void kernel_launch(void* const* d_in, const int* in_sizes, int n_in,
                              void* d_out, int out_size)
{
    const float* x   = (const float*)d_in[0];
    const float* Wq  = (const float*)d_in[1];
    const float* bq  = (const float*)d_in[2];
    const float* Wk  = (const float*)d_in[3];
    const float* bk  = (const float*)d_in[4];
    const float* Wv  = (const float*)d_in[5];
    const float* bv  = (const float*)d_in[6];
    const float* Wo  = (const float*)d_in[7];
    const float* bo  = (const float*)d_in[8];
    const float* W1  = (const float*)d_in[9];
    const float* b1  = (const float*)d_in[10];
    const float* W2  = (const float*)d_in[11];
    const float* b2  = (const float*)d_in[12];
    const float* g1  = (const float*)d_in[13];
    const float* be1 = (const float*)d_in[14];
    const float* g2  = (const float*)d_in[15];
    const float* be2 = (const float*)d_in[16];
    float* out = (float*)d_out;

    __half *xh,*qh,*kh,*vh,*ctxh,*x1h,*hh;
    __half *wqT,*wkT,*wvT,*woT,*w1T,*w2T;
    float *ao,*x1,*mlp;
    cudaGetSymbolAddress((void**)&xh,   g_xh);
    cudaGetSymbolAddress((void**)&qh,   g_qh);
    cudaGetSymbolAddress((void**)&kh,   g_kh);
    cudaGetSymbolAddress((void**)&vh,   g_vh);
    cudaGetSymbolAddress((void**)&ctxh, g_ctxh);
    cudaGetSymbolAddress((void**)&x1h,  g_x1h);
    cudaGetSymbolAddress((void**)&hh,   g_hh);
    cudaGetSymbolAddress((void**)&ao,   g_ao);
    cudaGetSymbolAddress((void**)&x1,   g_x1);
    cudaGetSymbolAddress((void**)&mlp,  g_mlp);
    cudaGetSymbolAddress((void**)&wqT,  g_wqT);
    cudaGetSymbolAddress((void**)&wkT,  g_wkT);
    cudaGetSymbolAddress((void**)&wvT,  g_wvT);
    cudaGetSymbolAddress((void**)&woT,  g_woT);
    cudaGetSymbolAddress((void**)&w1T,  g_w1T);
    cudaGetSymbolAddress((void**)&w2T,  g_w2T);

    cudaFuncSetAttribute(tgemm_k<1,0,1>, cudaFuncAttributeMaxDynamicSharedMemorySize, GEMM_SMEM_BYTES);
    cudaFuncSetAttribute(tgemm_k<0,0,0>, cudaFuncAttributeMaxDynamicSharedMemorySize, GEMM_SMEM_BYTES);
    cudaFuncSetAttribute(tgemm_k<0,1,1>, cudaFuncAttributeMaxDynamicSharedMemorySize, GEMM_SMEM_BYTES);
    cudaFuncSetAttribute(attn_k,         cudaFuncAttributeMaxDynamicSharedMemorySize, ATTN_SMEM_BYTES);

    // --- pre-pass: round x + transpose/round weights to fp16 ---
    {
        int n = TOK*DIM/4;
        roundh_k<<<(n+255)/256, 256>>>(x, xh, n);
        dim3 tg(DIM/32, DIM/32, 2);
        troundT2_k<<<tg, 256>>>(Wq, wqT, Wk, wkT, DIM, DIM);
        troundT2_k<<<tg, 256>>>(Wv, wvT, Wo, woT, DIM, DIM);
        dim3 tg12(HID/32, HID/32, 2);
        troundT12_k<<<tg12, 256>>>(W1, w1T, W2, w2T);
    }

    const int mtiles = (TOK + 127)/128;   // 99

    // --- fused QKV projection (half out, head-split; q pre-scaled) ---
    {
        dim3 grid(DIM/128, mtiles, 3);
        tgemm_k<1,0,1><<<grid, 256, GEMM_SMEM_BYTES>>>(xh, wqT, wkT, wvT, bq, bk, bv,
                                                       qh, kh, vh, TOK, DIM, DIM,
                                                       0.125f, 1.0f, 1.0f);
    }

    // --- fused attention -> ctx (half) ---
    attn_k<<<BH*4, 512, ATTN_SMEM_BYTES>>>(qh, kh, vh, ctxh);

    // --- attn_out = ctx @ Wo + bo (float out) ---
    {
        dim3 grid(DIM/128, mtiles, 1);
        tgemm_k<0,0,0><<<grid, 256, GEMM_SMEM_BYTES>>>(ctxh, woT, woT, woT, bo, bo, bo,
                                                       ao, ao, ao, TOK, DIM, DIM,
                                                       1.0f, 1.0f, 1.0f);
    }

    // --- x1 = x + LN(attn_out); half copy for MLP1 ---
    add_ln_k<<<TOK, 192>>>(x, ao, g1, be1, x1, x1h);

    // --- h = gelu(x1 @ W1 + b1) (half out) ---
    {
        dim3 grid(HID/128, mtiles, 1);
        tgemm_k<0,1,1><<<grid, 256, GEMM_SMEM_BYTES>>>(x1h, w1T, w1T, w1T, b1, b1, b1,
                                                       hh, hh, hh, TOK, HID, DIM,
                                                       1.0f, 1.0f, 1.0f);
    }

    // --- mlp = h @ W2 + b2 (float out) ---
    {
        dim3 grid(DIM/128, mtiles, 1);
        tgemm_k<0,0,0><<<grid, 256, GEMM_SMEM_BYTES>>>(hh, w2T, w2T, w2T, b2, b2, b2,
                                                       mlp, mlp, mlp, TOK, DIM, HID,
                                                       1.0f, 1.0f, 1.0f);
    }

    // --- out = x1 + LN(mlp) ---
    add_ln_k<<<TOK, 192>>>(x1, mlp, g2, be2, out, nullptr);
}

// round 14
// speedup vs baseline: 2.3075x; 1.1455x over previous
#include <cuda_runtime.h>
#include <cuda_fp16.h>
#include <math.h>
#include <stdint.h>

// ---------------- problem constants ----------------
#define BATCH   64
#define SEQ     197
#define TOK     (BATCH*SEQ)      // 12608
#define DIM     768
#define NHEAD   12
#define HDIM    64
#define HID     3072
#define BH      (BATCH*NHEAD)    // 768
#define LN_EPS  1e-6f

// ---------------- scratch (device globals) ----------------
__device__ __half g_xh  [(long)TOK*DIM];
__device__ __half g_qh  [(long)BH*SEQ*HDIM];
__device__ __half g_kh  [(long)BH*SEQ*HDIM];
__device__ __half g_vh  [(long)BH*SEQ*HDIM];
__device__ __half g_ctxh[(long)TOK*DIM];
__device__ __half g_x1h [(long)TOK*DIM];
__device__ __half g_hh  [(long)TOK*HID];
__device__ float  g_ao  [(long)TOK*DIM];
__device__ float  g_x1  [(long)TOK*DIM];
__device__ float  g_mlp [(long)TOK*DIM];
// transposed + fp16-rounded weights: [N][K]
__device__ __half g_wqT[DIM*DIM];
__device__ __half g_wkT[DIM*DIM];
__device__ __half g_wvT[DIM*DIM];
__device__ __half g_woT[DIM*DIM];
__device__ __half g_w1T[(long)HID*DIM];
__device__ __half g_w2T[(long)DIM*HID];

__device__ __forceinline__ float gelu_exact(float v) {
    return 0.5f * v * (1.f + erff(v * 0.70710678118654752f));
}
__device__ __forceinline__ void cpa16(uint32_t dst, const void* src) {
    asm volatile("cp.async.cg.shared.global [%0], [%1], 16;" :: "r"(dst), "l"(src) : "memory");
}
__device__ __forceinline__ void ldsm4(uint32_t addr, uint32_t& r0, uint32_t& r1,
                                      uint32_t& r2, uint32_t& r3) {
    asm volatile("ldmatrix.sync.aligned.m8n8.x4.shared.b16 {%0,%1,%2,%3}, [%4];"
                 : "=r"(r0), "=r"(r1), "=r"(r2), "=r"(r3) : "r"(addr));
}
__device__ __forceinline__ void ldsm4t(uint32_t addr, uint32_t& r0, uint32_t& r1,
                                       uint32_t& r2, uint32_t& r3) {
    asm volatile("ldmatrix.sync.aligned.m8n8.x4.trans.shared.b16 {%0,%1,%2,%3}, [%4];"
                 : "=r"(r0), "=r"(r1), "=r"(r2), "=r"(r3) : "r"(addr));
}
__device__ __forceinline__ void mma_f16(float* c, uint32_t a0, uint32_t a1,
                                        uint32_t a2, uint32_t a3,
                                        uint32_t b0, uint32_t b1) {
    asm volatile("mma.sync.aligned.m16n8k16.row.col.f32.f16.f16.f32 "
                 "{%0,%1,%2,%3}, {%4,%5,%6,%7}, {%8,%9}, {%0,%1,%2,%3};"
                 : "+f"(c[0]), "+f"(c[1]), "+f"(c[2]), "+f"(c[3])
                 : "r"(a0), "r"(a1), "r"(a2), "r"(a3), "r"(b0), "r"(b1));
}
__device__ __forceinline__ uint4 pack8h(float v0, float v1, float v2, float v3,
                                        float v4, float v5, float v6, float v7) {
    union { __half2 h[4]; uint4 u; } pk;
    pk.h[0] = __floats2half2_rn(v0, v1);
    pk.h[1] = __floats2half2_rn(v2, v3);
    pk.h[2] = __floats2half2_rn(v4, v5);
    pk.h[3] = __floats2half2_rn(v6, v7);
    return pk.u;
}

// ---------------- float -> fp16 rounding kernel ----------------
__global__ void roundh_k(const float* __restrict__ src, __half* __restrict__ dst, int n4)
{
    int i = blockIdx.x*blockDim.x + threadIdx.x;
    if (i < n4) {
        float4 v = reinterpret_cast<const float4*>(src)[i];
        union { __half2 h[2]; uint2 u; } pk;
        pk.h[0] = __floats2half2_rn(v.x, v.y);
        pk.h[1] = __floats2half2_rn(v.z, v.w);
        reinterpret_cast<uint2*>(dst)[i] = pk.u;
    }
}

// ---------------- transpose + fp16-round: src[K][N] -> dst[N][K] ----------------
__global__ void troundT2_k(const float* __restrict__ s0, __half* __restrict__ d0,
                           const float* __restrict__ s1, __half* __restrict__ d1,
                           int K, int N)
{
    const float* src = blockIdx.z ? s1 : s0;
    __half*      dst = blockIdx.z ? d1 : d0;
    __shared__ float t[32][33];
    const int n0 = blockIdx.x*32, k0 = blockIdx.y*32;
    const int tx = threadIdx.x & 31, tg = threadIdx.x >> 5;
    #pragma unroll
    for (int i=0;i<4;i++) {
        int r = tg + i*8;
        t[r][tx] = src[(size_t)(k0+r)*N + n0 + tx];
    }
    __syncthreads();
    #pragma unroll
    for (int i=0;i<4;i++) {
        int r = tg + i*8;
        dst[(size_t)(n0+r)*K + k0 + tx] = __float2half_rn(t[tx][r]);
    }
}

__global__ void troundT12_k(const float* __restrict__ s0, __half* __restrict__ d0,
                            const float* __restrict__ s1, __half* __restrict__ d1)
{
    int K, N;
    const float* src;
    __half* dst;
    if (blockIdx.z == 0) {
        if (blockIdx.x >= HID/32 || blockIdx.y >= DIM/32) return;
        src = s0; dst = d0; K = DIM; N = HID;
    } else {
        if (blockIdx.x >= DIM/32 || blockIdx.y >= HID/32) return;
        src = s1; dst = d1; K = HID; N = DIM;
    }
    __shared__ float t[32][33];
    const int n0 = blockIdx.x*32, k0 = blockIdx.y*32;
    const int tx = threadIdx.x & 31, tg = threadIdx.x >> 5;
    #pragma unroll
    for (int i=0;i<4;i++) {
        int r = tg + i*8;
        t[r][tx] = src[(size_t)(k0+r)*N + n0 + tx];
    }
    __syncthreads();
    #pragma unroll
    for (int i=0;i<4;i++) {
        int r = tg + i*8;
        dst[(size_t)(n0+r)*K + k0 + tx] = __float2half_rn(t[tx][r]);
    }
}

// =====================================================================
// FP16 GEMM via ldmatrix + mma.m16n8k16 (fp32 accumulate).
// 128x128x64 tiles, 8 warps (64x32 warp tiles), 2 CTAs/SM.
// 3-stage cp.async pipeline, single __syncthreads per k-step.
// OUTMODE: 0 plain; 1 head-split. EPI: 1 GELU. OUTHALF: half vs float out.
// Requires K%64==0, N%128==0.
// =====================================================================
#define APITCH 72                             // halves per row (64 + 8 pad)
#define STAGE_BYTES (128*APITCH*2*2)          // A+B = 36864
#define GEMM_SMEM_BYTES (3*STAGE_BYTES)       // 110592; epilogue 67584 fits

template<int OUTMODE,int EPI,int OUTHALF>
__launch_bounds__(256, 2)
__global__ void tgemm_k(const __half* __restrict__ A,
                        const __half* __restrict__ B0, const __half* __restrict__ B1, const __half* __restrict__ B2,
                        const float* __restrict__ c0, const float* __restrict__ c1, const float* __restrict__ c2,
                        void* __restrict__ D0, void* __restrict__ D1, void* __restrict__ D2,
                        int M, int N, int K, float a0, float a1, float a2)
{
    extern __shared__ char smc[];
    float* smf = reinterpret_cast<float*>(smc);
    const uint32_t smBase = (uint32_t)__cvta_generic_to_shared(smc);

    const int z = blockIdx.z;
    const __half* Bt  = (z==0) ? B0 : (z==1) ? B1 : B2;
    const float* bias = (z==0) ? c0 : (z==1) ? c1 : c2;
    void*        Dv   = (z==0) ? D0 : (z==1) ? D1 : D2;
    const float alpha = (z==0) ? a0 : (z==1) ? a1 : a2;

    const int tileM = blockIdx.y * 128;
    const int tileN = blockIdx.x * 128;
    const int tid   = threadIdx.x;
    const int warpId= tid >> 5;
    const int lane  = tid & 31;
    const int wm    = warpId >> 2;      // 0..1
    const int wn    = warpId & 3;       // 0..3

    // cp.async mapping: 8 threads per 64-half row
    const int ldRow = tid >> 3;         // 0..31
    const int ldCol = (tid & 7) << 3;   // 0..56 halves

    const __half* aPtr[4];
    #pragma unroll
    for (int t=0;t<4;t++) {
        int gm = tileM + t*32 + ldRow;
        if (gm > M-1) gm = M-1;
        aPtr[t] = A + (size_t)gm*K + ldCol;
    }
    const __half* bPtr[4];
    #pragma unroll
    for (int t=0;t<4;t++)
        bPtr[t] = Bt + (size_t)(tileN + t*32 + ldRow)*K + ldCol;

    const int rowOff = (lane & 7) + ((lane >> 3) & 1) * 8;
    const int kOff   = (lane >> 4) * 8;   // halves

    const uint32_t aAddr0 = smBase + (uint32_t)(((wm*64 + rowOff)*APITCH + kOff) * 2);
    const uint32_t bAddr0 = smBase + (uint32_t)((128*APITCH + (wn*32 + rowOff)*APITCH + kOff) * 2);

    float acc[4][4][4];
    #pragma unroll
    for (int i=0;i<4;i++)
        #pragma unroll
        for (int j=0;j<4;j++)
            #pragma unroll
            for (int t=0;t<4;t++) acc[i][j][t] = 0.f;

    auto loadStage = [&](int k0, int st) {
        const uint32_t ab = smBase + (uint32_t)st*STAGE_BYTES;
        const uint32_t bb = ab + 128*APITCH*2;
        #pragma unroll
        for (int t=0;t<4;t++)
            cpa16(ab + (uint32_t)(((t*32 + ldRow)*APITCH + ldCol)*2), aPtr[t] + k0);
        #pragma unroll
        for (int t=0;t<4;t++)
            cpa16(bb + (uint32_t)(((t*32 + ldRow)*APITCH + ldCol)*2), bPtr[t] + k0);
        asm volatile("cp.async.commit_group;" ::: "memory");
    };

    const int NS = K >> 6;
    loadStage(0, 0);
    if (NS > 1) loadStage(64, 1);

    int st = 0;
    for (int s = 0; s < NS; s++) {
        if (s + 1 < NS) asm volatile("cp.async.wait_group 1;" ::: "memory");
        else            asm volatile("cp.async.wait_group 0;" ::: "memory");
        __syncthreads();

        if (s + 2 < NS) {
            int nst = st + 2; if (nst >= 3) nst -= 3;
            loadStage((s+2) << 6, nst);
        }

        const uint32_t aS = aAddr0 + (uint32_t)st*STAGE_BYTES;
        const uint32_t bS = bAddr0 + (uint32_t)st*STAGE_BYTES;
        #pragma unroll
        for (int ks=0; ks<4; ks++) {
            uint32_t a[4][4], b[2][4];
            #pragma unroll
            for (int mb=0; mb<4; mb++)
                ldsm4(aS + (uint32_t)(mb*16*APITCH*2 + ks*32), a[mb][0], a[mb][1], a[mb][2], a[mb][3]);
            #pragma unroll
            for (int nb=0; nb<2; nb++)
                ldsm4(bS + (uint32_t)(nb*16*APITCH*2 + ks*32), b[nb][0], b[nb][1], b[nb][2], b[nb][3]);
            #pragma unroll
            for (int mb=0; mb<4; mb++)
                #pragma unroll
                for (int j=0; j<4; j++)
                    mma_f16(acc[mb][j], a[mb][0], a[mb][1], a[mb][2], a[mb][3],
                            b[j>>1][j&1], b[j>>1][(j&1)+2]);
        }
        if (++st == 3) st = 0;
    }
    __syncthreads();

    // ---- epilogue: stage 128x128 fp32 tile in smem (pitch 132) ----
    {
        const int r0 = lane >> 2;
        const int cb = 2*(lane & 3);
        #pragma unroll
        for (int mb=0; mb<4; mb++) {
            #pragma unroll
            for (int j=0; j<4; j++) {
                int row = wm*64 + mb*16 + r0;
                int col = wn*32 + j*8 + cb;
                *reinterpret_cast<float2*>(&smf[row*132 + col])     = make_float2(acc[mb][j][0], acc[mb][j][1]);
                *reinterpret_cast<float2*>(&smf[(row+8)*132 + col]) = make_float2(acc[mb][j][2], acc[mb][j][3]);
            }
        }
    }
    __syncthreads();

    {
        const int row = tid >> 1;
        const int gm  = tileM + row;
        if (gm < M) {
            int b = 0, s = 0;
            if (OUTMODE == 1) { b = gm / SEQ; s = gm - b*SEQ; }
            if (OUTHALF == 0) {
                float* C = reinterpret_cast<float*>(Dv);
                #pragma unroll
                for (int f=0; f<16; f++) {
                    int c  = (tid & 1)*64 + f*4;
                    int gn = tileN + c;
                    float4 v = *reinterpret_cast<const float4*>(&smf[row*132 + c]);
                    v.x = (v.x + bias[gn  ]) * alpha;
                    v.y = (v.y + bias[gn+1]) * alpha;
                    v.z = (v.z + bias[gn+2]) * alpha;
                    v.w = (v.w + bias[gn+3]) * alpha;
                    if (EPI == 1) {
                        v.x = gelu_exact(v.x); v.y = gelu_exact(v.y);
                        v.z = gelu_exact(v.z); v.w = gelu_exact(v.w);
                    }
                    *reinterpret_cast<float4*>(&C[(size_t)gm*N + gn]) = v;
                }
            } else {
                __half* C = reinterpret_cast<__half*>(Dv);
                #pragma unroll
                for (int f=0; f<8; f++) {
                    int c  = (tid & 1)*64 + f*8;
                    int gn = tileN + c;
                    float4 v0 = *reinterpret_cast<const float4*>(&smf[row*132 + c]);
                    float4 v1 = *reinterpret_cast<const float4*>(&smf[row*132 + c + 4]);
                    float w0 = (v0.x + bias[gn  ]) * alpha;
                    float w1 = (v0.y + bias[gn+1]) * alpha;
                    float w2 = (v0.z + bias[gn+2]) * alpha;
                    float w3 = (v0.w + bias[gn+3]) * alpha;
                    float w4 = (v1.x + bias[gn+4]) * alpha;
                    float w5 = (v1.y + bias[gn+5]) * alpha;
                    float w6 = (v1.z + bias[gn+6]) * alpha;
                    float w7 = (v1.w + bias[gn+7]) * alpha;
                    if (EPI == 1) {
                        w0 = gelu_exact(w0); w1 = gelu_exact(w1);
                        w2 = gelu_exact(w2); w3 = gelu_exact(w3);
                        w4 = gelu_exact(w4); w5 = gelu_exact(w5);
                        w6 = gelu_exact(w6); w7 = gelu_exact(w7);
                    }
                    uint4 u = pack8h(w0,w1,w2,w3,w4,w5,w6,w7);
                    if (OUTMODE == 0) {
                        *reinterpret_cast<uint4*>(&C[(size_t)gm*N + gn]) = u;
                    } else {
                        int h = gn >> 6, dd = gn & 63;
                        size_t orow = (size_t)(b*NHEAD + h)*SEQ + s;
                        *reinterpret_cast<uint4*>(&C[orow*HDIM + dd]) = u;
                    }
                }
            }
        }
    }
}

// =====================================================================
// Fused attention, fp16. One CTA per (bh, s-tile), 512 threads.
// Kh [t][72h], Vh [t][72h] (both d-contig, vectorized loads);
// PV uses ldmatrix.trans on Vh. Qh/O [64][72h]; Sf fp32 [64][212];
// Ph [64][216h].
// =====================================================================
#define AT_KP 72
#define AT_TP 216
#define AT_SP 212
#define OFFB_K 0
#define OFFB_V (208*AT_KP*2)                  // 29952
#define OFFB_Q (OFFB_V + 208*AT_KP*2)         // 59904
#define OFFB_S (OFFB_Q + 64*AT_KP*2)          // 69120
#define OFFB_P (OFFB_S + 64*AT_SP*4)          // 123392
#define ATTN_SMEM_BYTES (OFFB_P + 64*AT_TP*2) // 151040

__launch_bounds__(512)
__global__ void attn_k(const __half* __restrict__ q, const __half* __restrict__ k,
                       const __half* __restrict__ v, __half* __restrict__ ctx)
{
    extern __shared__ char smc[];
    const uint32_t smBase = (uint32_t)__cvta_generic_to_shared(smc);
    __half* Kh = reinterpret_cast<__half*>(smc + OFFB_K);
    __half* Vh = reinterpret_cast<__half*>(smc + OFFB_V);
    __half* Qh = reinterpret_cast<__half*>(smc + OFFB_Q);
    float*  Sf = reinterpret_cast<float*>(smc + OFFB_S);
    __half* Ph = reinterpret_cast<__half*>(smc + OFFB_P);

    const int bh   = blockIdx.x >> 2;
    const int tile = blockIdx.x & 3;
    const int s0   = tile * 64;
    const int valid = (SEQ - s0) < 64 ? (SEQ - s0) : 64;
    const int miMax = (valid + 15) >> 4;

    const int b  = bh / NHEAD;
    const int h  = bh - b*NHEAD;
    const int tid    = threadIdx.x;
    const int warpId = tid >> 5;
    const int lane   = tid & 31;

    const __half* qb = q + (size_t)bh*SEQ*HDIM;
    const __half* kb = k + (size_t)bh*SEQ*HDIM;
    const __half* vb = v + (size_t)bh*SEQ*HDIM;

    const int rowOff = (lane & 7) + ((lane >> 3) & 1) * 8;
    const int kOff   = (lane >> 4) * 8;
    const int r0 = lane >> 2;
    const int cb = 2*(lane & 3);

    const uint4 zero4 = make_uint4(0u,0u,0u,0u);

    // K and V [t][d] direct, vectorized
    for (int idx = tid; idx < 208*8; idx += 512) {
        int t = idx >> 3, f = idx & 7;
        uint4 kv = (t < SEQ) ? *reinterpret_cast<const uint4*>(kb + (size_t)t*HDIM + f*8) : zero4;
        uint4 vv = (t < SEQ) ? *reinterpret_cast<const uint4*>(vb + (size_t)t*HDIM + f*8) : zero4;
        *reinterpret_cast<uint4*>(Kh + t*AT_KP + f*8) = kv;
        *reinterpret_cast<uint4*>(Vh + t*AT_KP + f*8) = vv;
    }
    // Q tile
    for (int idx = tid; idx < 64*8; idx += 512) {
        int r = idx >> 3, f = idx & 7;
        int s = s0 + r;
        uint4 val = (s < SEQ) ? *reinterpret_cast<const uint4*>(qb + (size_t)s*HDIM + f*8) : zero4;
        *reinterpret_cast<uint4*>(Qh + r*AT_KP + f*8) = val;
    }
    __syncthreads();

    // ---- scores: miMax x 13 warp tiles (Q non-trans A, K non-trans B) ----
    for (int t = warpId; t < miMax*13; t += 16) {
        int mi = t / 13, ni = t - (t/13)*13;
        float c0[4] = {0.f,0.f,0.f,0.f}, c1[4] = {0.f,0.f,0.f,0.f};
        const uint32_t aAddr = smBase + OFFB_Q + (uint32_t)(((mi*16 + rowOff)*AT_KP + kOff)*2);
        const uint32_t bAddr = smBase + OFFB_K + (uint32_t)(((ni*16 + rowOff)*AT_KP + kOff)*2);
        #pragma unroll
        for (int ks=0; ks<4; ks++) {
            uint32_t a0,a1,a2,a3, b0,b1,b2,b3;
            ldsm4(aAddr + ks*32, a0,a1,a2,a3);
            ldsm4(bAddr + ks*32, b0,b1,b2,b3);
            mma_f16(c0, a0,a1,a2,a3, b0,b2);
            mma_f16(c1, a0,a1,a2,a3, b1,b3);
        }
        {
            int row = mi*16 + r0, col = ni*16 + cb;
            *reinterpret_cast<float2*>(&Sf[row*AT_SP + col])         = make_float2(c0[0], c0[1]);
            *reinterpret_cast<float2*>(&Sf[(row+8)*AT_SP + col])     = make_float2(c0[2], c0[3]);
            *reinterpret_cast<float2*>(&Sf[row*AT_SP + col + 8])     = make_float2(c1[0], c1[1]);
            *reinterpret_cast<float2*>(&Sf[(row+8)*AT_SP + col + 8]) = make_float2(c1[2], c1[3]);
        }
    }
    __syncthreads();

    // ---- softmax: fp32 in Sf, fp16 out to Ph ----
    for (int rr = 0; rr < miMax; rr++) {
        int r = rr*16 + warpId;
        float* rowp = &Sf[r*AT_SP];
        float x[7];
        float m = -1e30f;
        #pragma unroll
        for (int i=0;i<7;i++) {
            int c = lane + i*32;
            x[i] = (c < SEQ) ? rowp[c] : -1e30f;
            m = fmaxf(m, x[i]);
        }
        #pragma unroll
        for (int o=16;o;o>>=1) m = fmaxf(m, __shfl_xor_sync(0xffffffffu, m, o));
        float sum = 0.f;
        #pragma unroll
        for (int i=0;i<7;i++) { x[i] = __expf(x[i] - m); sum += x[i]; }
        #pragma unroll
        for (int o=16;o;o>>=1) sum += __shfl_xor_sync(0xffffffffu, sum, o);
        float inv = 1.f / sum;
        #pragma unroll
        for (int i=0;i<7;i++) {
            int c = lane + i*32;
            if (c < SEQ)      Ph[r*AT_TP + c] = __float2half_rn(x[i]*inv);
            else if (c < 208) Ph[r*AT_TP + c] = __float2half(0.f);
        }
    }
    __syncthreads();

    // ---- O = P @ V: miMax*4 warp tiles; V via ldmatrix.trans ----
    if (warpId < miMax*4) {
        int mi = warpId >> 2, ni = warpId & 3;
        float c0[4] = {0.f,0.f,0.f,0.f}, c1[4] = {0.f,0.f,0.f,0.f};
        const uint32_t aAddr = smBase + OFFB_P + (uint32_t)(((mi*16 + rowOff)*AT_TP + kOff)*2);
        // V [t][d]: rows = k(t), cols = n(d); trans delivers B fragments.
        const uint32_t bAddr = smBase + OFFB_V + (uint32_t)((rowOff*AT_KP + ni*16 + kOff)*2);
        #pragma unroll
        for (int ks=0; ks<13; ks++) {
            uint32_t a0,a1,a2,a3, b0,b1,b2,b3;
            ldsm4 (aAddr + ks*32,               a0,a1,a2,a3);
            ldsm4t(bAddr + (uint32_t)(ks*16*AT_KP*2), b0,b1,b2,b3);
            // trans pairing: n-half0 = (b0,b1), n-half1 = (b2,b3)
            mma_f16(c0, a0,a1,a2,a3, b0,b1);
            mma_f16(c1, a0,a1,a2,a3, b2,b3);
        }
        {
            int row = mi*16 + r0, col = ni*16 + cb;
            *reinterpret_cast<__half2*>(Qh + row*AT_KP + col)       = __floats2half2_rn(c0[0], c0[1]);
            *reinterpret_cast<__half2*>(Qh + (row+8)*AT_KP + col)   = __floats2half2_rn(c0[2], c0[3]);
            *reinterpret_cast<__half2*>(Qh + row*AT_KP + col+8)     = __floats2half2_rn(c1[0], c1[1]);
            *reinterpret_cast<__half2*>(Qh + (row+8)*AT_KP + col+8) = __floats2half2_rn(c1[2], c1[3]);
        }
    }
    __syncthreads();

    // ---- write ctx rows (half) ----
    for (int idx = tid; idx < valid*8; idx += 512) {
        int r = idx >> 3, f = idx & 7;
        int s = s0 + r;
        uint4 val = *reinterpret_cast<const uint4*>(Qh + r*AT_KP + f*8);
        *reinterpret_cast<uint4*>(ctx + ((size_t)(b*SEQ + s))*DIM + h*HDIM + f*8) = val;
    }
}

// ---------------- residual + LayerNorm (float4; optional half copy) ----------------
__launch_bounds__(192)
__global__ void add_ln_k(const float* __restrict__ x, const float* __restrict__ y,
                         const float* __restrict__ g, const float* __restrict__ be,
                         float* __restrict__ out, __half* __restrict__ outR)
{
    const int r = blockIdx.x;
    const int t = threadIdx.x;
    const float4 yv = *reinterpret_cast<const float4*>(&y[(size_t)r*DIM + t*4]);

    float s  = yv.x + yv.y + yv.z + yv.w;
    float sq = yv.x*yv.x + yv.y*yv.y + yv.z*yv.z + yv.w*yv.w;

    __shared__ float red[12];
    #pragma unroll
    for (int o=16;o;o>>=1) { s += __shfl_xor_sync(0xffffffffu, s, o); sq += __shfl_xor_sync(0xffffffffu, sq, o); }
    int w = t >> 5, lane = t & 31;
    if (lane == 0) { red[w] = s; red[w+6] = sq; }
    __syncthreads();
    if (t < 32) {
        s  = (lane < 6) ? red[lane]     : 0.f;
        sq = (lane < 6) ? red[lane + 6] : 0.f;
        #pragma unroll
        for (int o=4;o;o>>=1) { s += __shfl_xor_sync(0xffffffffu, s, o); sq += __shfl_xor_sync(0xffffffffu, sq, o); }
        if (lane == 0) { red[0] = s; red[1] = sq; }
    }
    __syncthreads();
    const float mu   = red[0] * (1.f/DIM);
    const float var  = red[1] * (1.f/DIM) - mu*mu;
    const float rstd = rsqrtf(var + LN_EPS);

    const float4 xv = *reinterpret_cast<const float4*>(&x[(size_t)r*DIM + t*4]);
    const float4 gv = *reinterpret_cast<const float4*>(&g[t*4]);
    const float4 bv = *reinterpret_cast<const float4*>(&be[t*4]);
    float4 o;
    o.x = xv.x + (yv.x - mu)*rstd*gv.x + bv.x;
    o.y = xv.y + (yv.y - mu)*rstd*gv.y + bv.y;
    o.z = xv.z + (yv.z - mu)*rstd*gv.z + bv.z;
    o.w = xv.w + (yv.w - mu)*rstd*gv.w + bv.w;
    *reinterpret_cast<float4*>(&out[(size_t)r*DIM + t*4]) = o;
    if (outR) {
        union { __half2 h[2]; uint2 u; } pk;
        pk.h[0] = __floats2half2_rn(o.x, o.y);
        pk.h[1] = __floats2half2_rn(o.z, o.w);
        *reinterpret_cast<uint2*>(outR + (size_t)r*DIM + t*4) = pk.u;
    }
}

// ---------------- launch ----------------
extern "C" void kernel_launch(void* const* d_in, const int* in_sizes, int n_in,
                              void* d_out, int out_size)
{
    const float* x   = (const float*)d_in[0];
    const float* Wq  = (const float*)d_in[1];
    const float* bq  = (const float*)d_in[2];
    const float* Wk  = (const float*)d_in[3];
    const float* bk  = (const float*)d_in[4];
    const float* Wv  = (const float*)d_in[5];
    const float* bv  = (const float*)d_in[6];
    const float* Wo  = (const float*)d_in[7];
    const float* bo  = (const float*)d_in[8];
    const float* W1  = (const float*)d_in[9];
    const float* b1  = (const float*)d_in[10];
    const float* W2  = (const float*)d_in[11];
    const float* b2  = (const float*)d_in[12];
    const float* g1  = (const float*)d_in[13];
    const float* be1 = (const float*)d_in[14];
    const float* g2  = (const float*)d_in[15];
    const float* be2 = (const float*)d_in[16];
    float* out = (float*)d_out;

    __half *xh,*qh,*kh,*vh,*ctxh,*x1h,*hh;
    __half *wqT,*wkT,*wvT,*woT,*w1T,*w2T;
    float *ao,*x1,*mlp;
    cudaGetSymbolAddress((void**)&xh,   g_xh);
    cudaGetSymbolAddress((void**)&qh,   g_qh);
    cudaGetSymbolAddress((void**)&kh,   g_kh);
    cudaGetSymbolAddress((void**)&vh,   g_vh);
    cudaGetSymbolAddress((void**)&ctxh, g_ctxh);
    cudaGetSymbolAddress((void**)&x1h,  g_x1h);
    cudaGetSymbolAddress((void**)&hh,   g_hh);
    cudaGetSymbolAddress((void**)&ao,   g_ao);
    cudaGetSymbolAddress((void**)&x1,   g_x1);
    cudaGetSymbolAddress((void**)&mlp,  g_mlp);
    cudaGetSymbolAddress((void**)&wqT,  g_wqT);
    cudaGetSymbolAddress((void**)&wkT,  g_wkT);
    cudaGetSymbolAddress((void**)&wvT,  g_wvT);
    cudaGetSymbolAddress((void**)&woT,  g_woT);
    cudaGetSymbolAddress((void**)&w1T,  g_w1T);
    cudaGetSymbolAddress((void**)&w2T,  g_w2T);

    cudaFuncSetAttribute(tgemm_k<1,0,1>, cudaFuncAttributeMaxDynamicSharedMemorySize, GEMM_SMEM_BYTES);
    cudaFuncSetAttribute(tgemm_k<0,0,0>, cudaFuncAttributeMaxDynamicSharedMemorySize, GEMM_SMEM_BYTES);
    cudaFuncSetAttribute(tgemm_k<0,1,1>, cudaFuncAttributeMaxDynamicSharedMemorySize, GEMM_SMEM_BYTES);
    cudaFuncSetAttribute(attn_k,         cudaFuncAttributeMaxDynamicSharedMemorySize, ATTN_SMEM_BYTES);

    // --- pre-pass: round x + transpose/round weights to fp16 ---
    {
        int n = TOK*DIM/4;
        roundh_k<<<(n+255)/256, 256>>>(x, xh, n);
        dim3 tg(DIM/32, DIM/32, 2);
        troundT2_k<<<tg, 256>>>(Wq, wqT, Wk, wkT, DIM, DIM);
        troundT2_k<<<tg, 256>>>(Wv, wvT, Wo, woT, DIM, DIM);
        dim3 tg12(HID/32, HID/32, 2);
        troundT12_k<<<tg12, 256>>>(W1, w1T, W2, w2T);
    }

    const int mtiles = (TOK + 127)/128;   // 99

    // --- fused QKV projection (half out, head-split; q pre-scaled) ---
    {
        dim3 grid(DIM/128, mtiles, 3);
        tgemm_k<1,0,1><<<grid, 256, GEMM_SMEM_BYTES>>>(xh, wqT, wkT, wvT, bq, bk, bv,
                                                       qh, kh, vh, TOK, DIM, DIM,
                                                       0.125f, 1.0f, 1.0f);
    }

    // --- fused attention -> ctx (half) ---
    attn_k<<<BH*4, 512, ATTN_SMEM_BYTES>>>(qh, kh, vh, ctxh);

    // --- attn_out = ctx @ Wo + bo (float out) ---
    {
        dim3 grid(DIM/128, mtiles, 1);
        tgemm_k<0,0,0><<<grid, 256, GEMM_SMEM_BYTES>>>(ctxh, woT, woT, woT, bo, bo, bo,
                                                       ao, ao, ao, TOK, DIM, DIM,
                                                       1.0f, 1.0f, 1.0f);
    }

    // --- x1 = x + LN(attn_out); half copy for MLP1 ---
    add_ln_k<<<TOK, 192>>>(x, ao, g1, be1, x1, x1h);

    // --- h = gelu(x1 @ W1 + b1) (half out) ---
    {
        dim3 grid(HID/128, mtiles, 1);
        tgemm_k<0,1,1><<<grid, 256, GEMM_SMEM_BYTES>>>(x1h, w1T, w1T, w1T, b1, b1, b1,
                                                       hh, hh, hh, TOK, HID, DIM,
                                                       1.0f, 1.0f, 1.0f);
    }

    // --- mlp = h @ W2 + b2 (float out) ---
    {
        dim3 grid(DIM/128, mtiles, 1);
        tgemm_k<0,0,0><<<grid, 256, GEMM_SMEM_BYTES>>>(hh, w2T, w2T, w2T, b2, b2, b2,
                                                       mlp, mlp, mlp, TOK, DIM, HID,
                                                       1.0f, 1.0f, 1.0f);
    }

    // --- out = x1 + LN(mlp) ---
    add_ln_k<<<TOK, 192>>>(x1, mlp, g2, be2, out, nullptr);
}

// round 15
// speedup vs baseline: 2.3203x; 1.0055x over previous
#include <cuda_runtime.h>
#include <cuda_fp16.h>
#include <math.h>
#include <stdint.h>

// ---------------- problem constants ----------------
#define BATCH   64
#define SEQ     197
#define TOK     (BATCH*SEQ)      // 12608
#define DIM     768
#define NHEAD   12
#define HDIM    64
#define HID     3072
#define BH      (BATCH*NHEAD)    // 768
#define LN_EPS  1e-6f

// ---------------- scratch (device globals) ----------------
__device__ __half g_xh  [(long)TOK*DIM];
__device__ __half g_qh  [(long)BH*SEQ*HDIM];
__device__ __half g_kh  [(long)BH*SEQ*HDIM];
__device__ __half g_vh  [(long)BH*SEQ*HDIM];
__device__ __half g_ctxh[(long)TOK*DIM];
__device__ __half g_x1h [(long)TOK*DIM];
__device__ __half g_hh  [(long)TOK*HID];
__device__ float  g_ao  [(long)TOK*DIM];
__device__ float  g_x1  [(long)TOK*DIM];
__device__ float  g_mlp [(long)TOK*DIM];
// transposed + fp16-rounded weights: [N][K]
__device__ __half g_wqT[DIM*DIM];
__device__ __half g_wkT[DIM*DIM];
__device__ __half g_wvT[DIM*DIM];
__device__ __half g_woT[DIM*DIM];
__device__ __half g_w1T[(long)HID*DIM];
__device__ __half g_w2T[(long)DIM*HID];

__device__ __forceinline__ float gelu_exact(float v) {
    return 0.5f * v * (1.f + erff(v * 0.70710678118654752f));
}
__device__ __forceinline__ void cpa16(uint32_t dst, const void* src) {
    asm volatile("cp.async.cg.shared.global [%0], [%1], 16;" :: "r"(dst), "l"(src) : "memory");
}
__device__ __forceinline__ void ldsm4(uint32_t addr, uint32_t& r0, uint32_t& r1,
                                      uint32_t& r2, uint32_t& r3) {
    asm volatile("ldmatrix.sync.aligned.m8n8.x4.shared.b16 {%0,%1,%2,%3}, [%4];"
                 : "=r"(r0), "=r"(r1), "=r"(r2), "=r"(r3) : "r"(addr));
}
__device__ __forceinline__ void ldsm4t(uint32_t addr, uint32_t& r0, uint32_t& r1,
                                       uint32_t& r2, uint32_t& r3) {
    asm volatile("ldmatrix.sync.aligned.m8n8.x4.trans.shared.b16 {%0,%1,%2,%3}, [%4];"
                 : "=r"(r0), "=r"(r1), "=r"(r2), "=r"(r3) : "r"(addr));
}
__device__ __forceinline__ void mma_f16(float* c, uint32_t a0, uint32_t a1,
                                        uint32_t a2, uint32_t a3,
                                        uint32_t b0, uint32_t b1) {
    asm volatile("mma.sync.aligned.m16n8k16.row.col.f32.f16.f16.f32 "
                 "{%0,%1,%2,%3}, {%4,%5,%6,%7}, {%8,%9}, {%0,%1,%2,%3};"
                 : "+f"(c[0]), "+f"(c[1]), "+f"(c[2]), "+f"(c[3])
                 : "r"(a0), "r"(a1), "r"(a2), "r"(a3), "r"(b0), "r"(b1));
}

// ---------------- float -> fp16 rounding kernel ----------------
__global__ void roundh_k(const float* __restrict__ src, __half* __restrict__ dst, int n4)
{
    int i = blockIdx.x*blockDim.x + threadIdx.x;
    if (i < n4) {
        float4 v = reinterpret_cast<const float4*>(src)[i];
        union { __half2 h[2]; uint2 u; } pk;
        pk.h[0] = __floats2half2_rn(v.x, v.y);
        pk.h[1] = __floats2half2_rn(v.z, v.w);
        reinterpret_cast<uint2*>(dst)[i] = pk.u;
    }
}

// ---------------- transpose + fp16-round: src[K][N] -> dst[N][K] ----------------
__global__ void troundT2_k(const float* __restrict__ s0, __half* __restrict__ d0,
                           const float* __restrict__ s1, __half* __restrict__ d1,
                           int K, int N)
{
    const float* src = blockIdx.z ? s1 : s0;
    __half*      dst = blockIdx.z ? d1 : d0;
    __shared__ float t[32][33];
    const int n0 = blockIdx.x*32, k0 = blockIdx.y*32;
    const int tx = threadIdx.x & 31, tg = threadIdx.x >> 5;
    #pragma unroll
    for (int i=0;i<4;i++) {
        int r = tg + i*8;
        t[r][tx] = src[(size_t)(k0+r)*N + n0 + tx];
    }
    __syncthreads();
    #pragma unroll
    for (int i=0;i<4;i++) {
        int r = tg + i*8;
        dst[(size_t)(n0+r)*K + k0 + tx] = __float2half_rn(t[tx][r]);
    }
}

// W1 [DIM][HID]->[HID][DIM] (z=0) and W2 [HID][DIM]->[DIM][HID] (z=1),
// tight grid (HID/32, DIM/32, 2) with index swap for z=1.
__global__ void troundT12_k(const float* __restrict__ s0, __half* __restrict__ d0,
                            const float* __restrict__ s1, __half* __restrict__ d1)
{
    int K, N, n0, k0;
    const float* src;
    __half* dst;
    if (blockIdx.z == 0) {
        src = s0; dst = d0; K = DIM; N = HID;
        n0 = blockIdx.x*32; k0 = blockIdx.y*32;
    } else {
        src = s1; dst = d1; K = HID; N = DIM;
        n0 = blockIdx.y*32; k0 = blockIdx.x*32;
    }
    __shared__ float t[32][33];
    const int tx = threadIdx.x & 31, tg = threadIdx.x >> 5;
    #pragma unroll
    for (int i=0;i<4;i++) {
        int r = tg + i*8;
        t[r][tx] = src[(size_t)(k0+r)*N + n0 + tx];
    }
    __syncthreads();
    #pragma unroll
    for (int i=0;i<4;i++) {
        int r = tg + i*8;
        dst[(size_t)(n0+r)*K + k0 + tx] = __float2half_rn(t[tx][r]);
    }
}

// =====================================================================
// FP16 GEMM via ldmatrix + mma.m16n8k16 (fp32 accumulate).
// 128x128x64 tiles, 8 warps (64x32 warp tiles), 2 CTAs/SM.
// 3-stage cp.async pipeline, single __syncthreads per k-step.
// OUTHALF=1: register epilogue math -> half2 smem staging -> uint4 stores.
// OUTHALF=0: fp32 smem staging -> float4 stores.
// =====================================================================
#define APITCH 72                             // halves per row (64 + 8 pad)
#define STAGE_BYTES (128*APITCH*2*2)          // A+B = 36864
#define GEMM_SMEM_BYTES (3*STAGE_BYTES)       // 110592; fp32 epilogue 67584 fits

template<int OUTMODE,int EPI,int OUTHALF>
__launch_bounds__(256, 2)
__global__ void tgemm_k(const __half* __restrict__ A,
                        const __half* __restrict__ B0, const __half* __restrict__ B1, const __half* __restrict__ B2,
                        const float* __restrict__ c0, const float* __restrict__ c1, const float* __restrict__ c2,
                        void* __restrict__ D0, void* __restrict__ D1, void* __restrict__ D2,
                        int M, int N, int K, float a0, float a1, float a2)
{
    extern __shared__ char smc[];
    float*  smf = reinterpret_cast<float*>(smc);
    __half* smh = reinterpret_cast<__half*>(smc);
    const uint32_t smBase = (uint32_t)__cvta_generic_to_shared(smc);

    const int z = blockIdx.z;
    const __half* Bt  = (z==0) ? B0 : (z==1) ? B1 : B2;
    const float* bias = (z==0) ? c0 : (z==1) ? c1 : c2;
    void*        Dv   = (z==0) ? D0 : (z==1) ? D1 : D2;
    const float alpha = (z==0) ? a0 : (z==1) ? a1 : a2;

    const int tileM = blockIdx.y * 128;
    const int tileN = blockIdx.x * 128;
    const int tid   = threadIdx.x;
    const int warpId= tid >> 5;
    const int lane  = tid & 31;
    const int wm    = warpId >> 2;      // 0..1
    const int wn    = warpId & 3;       // 0..3

    const int ldRow = tid >> 3;         // 0..31
    const int ldCol = (tid & 7) << 3;   // 0..56 halves

    const __half* aPtr[4];
    #pragma unroll
    for (int t=0;t<4;t++) {
        int gm = tileM + t*32 + ldRow;
        if (gm > M-1) gm = M-1;
        aPtr[t] = A + (size_t)gm*K + ldCol;
    }
    const __half* bPtr[4];
    #pragma unroll
    for (int t=0;t<4;t++)
        bPtr[t] = Bt + (size_t)(tileN + t*32 + ldRow)*K + ldCol;

    const int rowOff = (lane & 7) + ((lane >> 3) & 1) * 8;
    const int kOff   = (lane >> 4) * 8;

    const uint32_t aAddr0 = smBase + (uint32_t)(((wm*64 + rowOff)*APITCH + kOff) * 2);
    const uint32_t bAddr0 = smBase + (uint32_t)((128*APITCH + (wn*32 + rowOff)*APITCH + kOff) * 2);

    float acc[4][4][4];
    #pragma unroll
    for (int i=0;i<4;i++)
        #pragma unroll
        for (int j=0;j<4;j++)
            #pragma unroll
            for (int t=0;t<4;t++) acc[i][j][t] = 0.f;

    auto loadStage = [&](int k0, int st) {
        const uint32_t ab = smBase + (uint32_t)st*STAGE_BYTES;
        const uint32_t bb = ab + 128*APITCH*2;
        #pragma unroll
        for (int t=0;t<4;t++)
            cpa16(ab + (uint32_t)(((t*32 + ldRow)*APITCH + ldCol)*2), aPtr[t] + k0);
        #pragma unroll
        for (int t=0;t<4;t++)
            cpa16(bb + (uint32_t)(((t*32 + ldRow)*APITCH + ldCol)*2), bPtr[t] + k0);
        asm volatile("cp.async.commit_group;" ::: "memory");
    };

    const int NS = K >> 6;
    loadStage(0, 0);
    if (NS > 1) loadStage(64, 1);

    int st = 0;
    for (int s = 0; s < NS; s++) {
        if (s + 1 < NS) asm volatile("cp.async.wait_group 1;" ::: "memory");
        else            asm volatile("cp.async.wait_group 0;" ::: "memory");
        __syncthreads();

        if (s + 2 < NS) {
            int nst = st + 2; if (nst >= 3) nst -= 3;
            loadStage((s+2) << 6, nst);
        }

        const uint32_t aS = aAddr0 + (uint32_t)st*STAGE_BYTES;
        const uint32_t bS = bAddr0 + (uint32_t)st*STAGE_BYTES;
        #pragma unroll
        for (int ks=0; ks<4; ks++) {
            uint32_t a[4][4], b[2][4];
            #pragma unroll
            for (int mb=0; mb<4; mb++)
                ldsm4(aS + (uint32_t)(mb*16*APITCH*2 + ks*32), a[mb][0], a[mb][1], a[mb][2], a[mb][3]);
            #pragma unroll
            for (int nb=0; nb<2; nb++)
                ldsm4(bS + (uint32_t)(nb*16*APITCH*2 + ks*32), b[nb][0], b[nb][1], b[nb][2], b[nb][3]);
            #pragma unroll
            for (int mb=0; mb<4; mb++)
                #pragma unroll
                for (int j=0; j<4; j++)
                    mma_f16(acc[mb][j], a[mb][0], a[mb][1], a[mb][2], a[mb][3],
                            b[j>>1][j&1], b[j>>1][(j&1)+2]);
        }
        if (++st == 3) st = 0;
    }
    __syncthreads();

    const int r0 = lane >> 2;
    const int cb = 2*(lane & 3);

    if (OUTHALF == 0) {
        // ---- fp32 staging epilogue (pitch 132) ----
        #pragma unroll
        for (int mb=0; mb<4; mb++) {
            #pragma unroll
            for (int j=0; j<4; j++) {
                int row = wm*64 + mb*16 + r0;
                int col = wn*32 + j*8 + cb;
                *reinterpret_cast<float2*>(&smf[row*132 + col])     = make_float2(acc[mb][j][0], acc[mb][j][1]);
                *reinterpret_cast<float2*>(&smf[(row+8)*132 + col]) = make_float2(acc[mb][j][2], acc[mb][j][3]);
            }
        }
        __syncthreads();
        const int row = tid >> 1;
        const int gm  = tileM + row;
        if (gm < M) {
            float* C = reinterpret_cast<float*>(Dv);
            #pragma unroll
            for (int f=0; f<16; f++) {
                int c  = (tid & 1)*64 + f*4;
                int gn = tileN + c;
                float4 v = *reinterpret_cast<const float4*>(&smf[row*132 + c]);
                v.x = (v.x + bias[gn  ]) * alpha;
                v.y = (v.y + bias[gn+1]) * alpha;
                v.z = (v.z + bias[gn+2]) * alpha;
                v.w = (v.w + bias[gn+3]) * alpha;
                if (EPI == 1) {
                    v.x = gelu_exact(v.x); v.y = gelu_exact(v.y);
                    v.z = gelu_exact(v.z); v.w = gelu_exact(v.w);
                }
                *reinterpret_cast<float4*>(&C[(size_t)gm*N + gn]) = v;
            }
        }
    } else {
        // ---- register epilogue math -> half2 staging (pitch 136 halves) ----
        float bx[4], by[4];
        #pragma unroll
        for (int j=0;j<4;j++) {
            int gn = tileN + wn*32 + j*8 + cb;
            bx[j] = bias[gn];
            by[j] = bias[gn+1];
        }
        #pragma unroll
        for (int mb=0; mb<4; mb++) {
            #pragma unroll
            for (int j=0; j<4; j++) {
                int row = wm*64 + mb*16 + r0;
                int col = wn*32 + j*8 + cb;
                float v0 = (acc[mb][j][0] + bx[j]) * alpha;
                float v1 = (acc[mb][j][1] + by[j]) * alpha;
                float v2 = (acc[mb][j][2] + bx[j]) * alpha;
                float v3 = (acc[mb][j][3] + by[j]) * alpha;
                if (EPI == 1) {
                    v0 = gelu_exact(v0); v1 = gelu_exact(v1);
                    v2 = gelu_exact(v2); v3 = gelu_exact(v3);
                }
                *reinterpret_cast<__half2*>(&smh[row*136 + col])     = __floats2half2_rn(v0, v1);
                *reinterpret_cast<__half2*>(&smh[(row+8)*136 + col]) = __floats2half2_rn(v2, v3);
            }
        }
        __syncthreads();
        const int row = tid >> 1;
        const int gm  = tileM + row;
        if (gm < M) {
            __half* C = reinterpret_cast<__half*>(Dv);
            int b = 0, s = 0;
            if (OUTMODE == 1) { b = gm / SEQ; s = gm - b*SEQ; }
            #pragma unroll
            for (int f=0; f<8; f++) {
                int c  = (tid & 1)*64 + f*8;
                int gn = tileN + c;
                uint4 u = *reinterpret_cast<const uint4*>(&smh[row*136 + c]);
                if (OUTMODE == 0) {
                    *reinterpret_cast<uint4*>(&C[(size_t)gm*N + gn]) = u;
                } else {
                    int h = gn >> 6, dd = gn & 63;
                    size_t orow = (size_t)(b*NHEAD + h)*SEQ + s;
                    *reinterpret_cast<uint4*>(&C[orow*HDIM + dd]) = u;
                }
            }
        }
    }
}

// =====================================================================
// Fused attention, fp16 (R14 configuration, proven).
// =====================================================================
#define AT_KP 72
#define AT_TP 216
#define AT_SP 212
#define OFFB_K 0
#define OFFB_V (208*AT_KP*2)
#define OFFB_Q (OFFB_V + 208*AT_KP*2)
#define OFFB_S (OFFB_Q + 64*AT_KP*2)
#define OFFB_P (OFFB_S + 64*AT_SP*4)
#define ATTN_SMEM_BYTES (OFFB_P + 64*AT_TP*2)

__launch_bounds__(512)
__global__ void attn_k(const __half* __restrict__ q, const __half* __restrict__ k,
                       const __half* __restrict__ v, __half* __restrict__ ctx)
{
    extern __shared__ char smc[];
    const uint32_t smBase = (uint32_t)__cvta_generic_to_shared(smc);
    __half* Kh = reinterpret_cast<__half*>(smc + OFFB_K);
    __half* Vh = reinterpret_cast<__half*>(smc + OFFB_V);
    __half* Qh = reinterpret_cast<__half*>(smc + OFFB_Q);
    float*  Sf = reinterpret_cast<float*>(smc + OFFB_S);
    __half* Ph = reinterpret_cast<__half*>(smc + OFFB_P);

    const int bh   = blockIdx.x >> 2;
    const int tile = blockIdx.x & 3;
    const int s0   = tile * 64;
    const int valid = (SEQ - s0) < 64 ? (SEQ - s0) : 64;
    const int miMax = (valid + 15) >> 4;

    const int b  = bh / NHEAD;
    const int h  = bh - b*NHEAD;
    const int tid    = threadIdx.x;
    const int warpId = tid >> 5;
    const int lane   = tid & 31;

    const __half* qb = q + (size_t)bh*SEQ*HDIM;
    const __half* kb = k + (size_t)bh*SEQ*HDIM;
    const __half* vb = v + (size_t)bh*SEQ*HDIM;

    const int rowOff = (lane & 7) + ((lane >> 3) & 1) * 8;
    const int kOff   = (lane >> 4) * 8;
    const int r0 = lane >> 2;
    const int cb = 2*(lane & 3);

    const uint4 zero4 = make_uint4(0u,0u,0u,0u);

    for (int idx = tid; idx < 208*8; idx += 512) {
        int t = idx >> 3, f = idx & 7;
        uint4 kv = (t < SEQ) ? *reinterpret_cast<const uint4*>(kb + (size_t)t*HDIM + f*8) : zero4;
        uint4 vv = (t < SEQ) ? *reinterpret_cast<const uint4*>(vb + (size_t)t*HDIM + f*8) : zero4;
        *reinterpret_cast<uint4*>(Kh + t*AT_KP + f*8) = kv;
        *reinterpret_cast<uint4*>(Vh + t*AT_KP + f*8) = vv;
    }
    for (int idx = tid; idx < 64*8; idx += 512) {
        int r = idx >> 3, f = idx & 7;
        int s = s0 + r;
        uint4 val = (s < SEQ) ? *reinterpret_cast<const uint4*>(qb + (size_t)s*HDIM + f*8) : zero4;
        *reinterpret_cast<uint4*>(Qh + r*AT_KP + f*8) = val;
    }
    __syncthreads();

    for (int t = warpId; t < miMax*13; t += 16) {
        int mi = t / 13, ni = t - (t/13)*13;
        float c0[4] = {0.f,0.f,0.f,0.f}, c1[4] = {0.f,0.f,0.f,0.f};
        const uint32_t aAddr = smBase + OFFB_Q + (uint32_t)(((mi*16 + rowOff)*AT_KP + kOff)*2);
        const uint32_t bAddr = smBase + OFFB_K + (uint32_t)(((ni*16 + rowOff)*AT_KP + kOff)*2);
        #pragma unroll
        for (int ks=0; ks<4; ks++) {
            uint32_t a0,a1,a2,a3, b0,b1,b2,b3;
            ldsm4(aAddr + ks*32, a0,a1,a2,a3);
            ldsm4(bAddr + ks*32, b0,b1,b2,b3);
            mma_f16(c0, a0,a1,a2,a3, b0,b2);
            mma_f16(c1, a0,a1,a2,a3, b1,b3);
        }
        {
            int row = mi*16 + r0, col = ni*16 + cb;
            *reinterpret_cast<float2*>(&Sf[row*AT_SP + col])         = make_float2(c0[0], c0[1]);
            *reinterpret_cast<float2*>(&Sf[(row+8)*AT_SP + col])     = make_float2(c0[2], c0[3]);
            *reinterpret_cast<float2*>(&Sf[row*AT_SP + col + 8])     = make_float2(c1[0], c1[1]);
            *reinterpret_cast<float2*>(&Sf[(row+8)*AT_SP + col + 8]) = make_float2(c1[2], c1[3]);
        }
    }
    __syncthreads();

    for (int rr = 0; rr < miMax; rr++) {
        int r = rr*16 + warpId;
        float* rowp = &Sf[r*AT_SP];
        float x[7];
        float m = -1e30f;
        #pragma unroll
        for (int i=0;i<7;i++) {
            int c = lane + i*32;
            x[i] = (c < SEQ) ? rowp[c] : -1e30f;
            m = fmaxf(m, x[i]);
        }
        #pragma unroll
        for (int o=16;o;o>>=1) m = fmaxf(m, __shfl_xor_sync(0xffffffffu, m, o));
        float sum = 0.f;
        #pragma unroll
        for (int i=0;i<7;i++) { x[i] = __expf(x[i] - m); sum += x[i]; }
        #pragma unroll
        for (int o=16;o;o>>=1) sum += __shfl_xor_sync(0xffffffffu, sum, o);
        float inv = 1.f / sum;
        #pragma unroll
        for (int i=0;i<7;i++) {
            int c = lane + i*32;
            if (c < SEQ)      Ph[r*AT_TP + c] = __float2half_rn(x[i]*inv);
            else if (c < 208) Ph[r*AT_TP + c] = __float2half(0.f);
        }
    }
    __syncthreads();

    if (warpId < miMax*4) {
        int mi = warpId >> 2, ni = warpId & 3;
        float c0[4] = {0.f,0.f,0.f,0.f}, c1[4] = {0.f,0.f,0.f,0.f};
        const uint32_t aAddr = smBase + OFFB_P + (uint32_t)(((mi*16 + rowOff)*AT_TP + kOff)*2);
        const uint32_t bAddr = smBase + OFFB_V + (uint32_t)((rowOff*AT_KP + ni*16 + kOff)*2);
        #pragma unroll
        for (int ks=0; ks<13; ks++) {
            uint32_t a0,a1,a2,a3, b0,b1,b2,b3;
            ldsm4 (aAddr + ks*32,                     a0,a1,a2,a3);
            ldsm4t(bAddr + (uint32_t)(ks*16*AT_KP*2), b0,b1,b2,b3);
            mma_f16(c0, a0,a1,a2,a3, b0,b1);
            mma_f16(c1, a0,a1,a2,a3, b2,b3);
        }
        {
            int row = mi*16 + r0, col = ni*16 + cb;
            *reinterpret_cast<__half2*>(Qh + row*AT_KP + col)       = __floats2half2_rn(c0[0], c0[1]);
            *reinterpret_cast<__half2*>(Qh + (row+8)*AT_KP + col)   = __floats2half2_rn(c0[2], c0[3]);
            *reinterpret_cast<__half2*>(Qh + row*AT_KP + col+8)     = __floats2half2_rn(c1[0], c1[1]);
            *reinterpret_cast<__half2*>(Qh + (row+8)*AT_KP + col+8) = __floats2half2_rn(c1[2], c1[3]);
        }
    }
    __syncthreads();

    for (int idx = tid; idx < valid*8; idx += 512) {
        int r = idx >> 3, f = idx & 7;
        int s = s0 + r;
        uint4 val = *reinterpret_cast<const uint4*>(Qh + r*AT_KP + f*8);
        *reinterpret_cast<uint4*>(ctx + ((size_t)(b*SEQ + s))*DIM + h*HDIM + f*8) = val;
    }
}

// ---------------- residual + LayerNorm: 2 rows per CTA, 384 threads ----------------
__launch_bounds__(384)
__global__ void add_ln_k(const float* __restrict__ x, const float* __restrict__ y,
                         const float* __restrict__ g, const float* __restrict__ be,
                         float* __restrict__ out, __half* __restrict__ outR, int rows)
{
    const int sub = threadIdx.x / 192;          // 0..1 -> row within pair
    const int t   = threadIdx.x - sub*192;      // 0..191
    const int r   = blockIdx.x*2 + sub;
    if (r >= rows) return;
    const float4 yv = *reinterpret_cast<const float4*>(&y[(size_t)r*DIM + t*4]);

    float s  = yv.x + yv.y + yv.z + yv.w;
    float sq = yv.x*yv.x + yv.y*yv.y + yv.z*yv.z + yv.w*yv.w;

    __shared__ float red[2][16];
    #pragma unroll
    for (int o=16;o;o>>=1) { s += __shfl_xor_sync(0xffffffffu, s, o); sq += __shfl_xor_sync(0xffffffffu, sq, o); }
    int w = t >> 5, lane = t & 31;              // w: 0..5 within sub-row
    if (lane == 0) { red[sub][w] = s; red[sub][w+8] = sq; }
    __syncthreads();
    if (t < 32) {
        s  = (lane < 6) ? red[sub][lane]     : 0.f;
        sq = (lane < 6) ? red[sub][lane + 8] : 0.f;
        #pragma unroll
        for (int o=4;o;o>>=1) { s += __shfl_xor_sync(0xffffffffu, s, o); sq += __shfl_xor_sync(0xffffffffu, sq, o); }
        if (lane == 0) { red[sub][0] = s; red[sub][1] = sq; }
    }
    __syncthreads();
    const float mu   = red[sub][0] * (1.f/DIM);
    const float var  = red[sub][1] * (1.f/DIM) - mu*mu;
    const float rstd = rsqrtf(var + LN_EPS);

    const float4 xv = *reinterpret_cast<const float4*>(&x[(size_t)r*DIM + t*4]);
    const float4 gv = *reinterpret_cast<const float4*>(&g[t*4]);
    const float4 bv = *reinterpret_cast<const float4*>(&be[t*4]);
    float4 o;
    o.x = xv.x + (yv.x - mu)*rstd*gv.x + bv.x;
    o.y = xv.y + (yv.y - mu)*rstd*gv.y + bv.y;
    o.z = xv.z + (yv.z - mu)*rstd*gv.z + bv.z;
    o.w = xv.w + (yv.w - mu)*rstd*gv.w + bv.w;
    *reinterpret_cast<float4*>(&out[(size_t)r*DIM + t*4]) = o;
    if (outR) {
        union { __half2 h[2]; uint2 u; } pk;
        pk.h[0] = __floats2half2_rn(o.x, o.y);
        pk.h[1] = __floats2half2_rn(o.z, o.w);
        *reinterpret_cast<uint2*>(outR + (size_t)r*DIM + t*4) = pk.u;
    }
}

// ---------------- launch ----------------
extern "C" void kernel_launch(void* const* d_in, const int* in_sizes, int n_in,
                              void* d_out, int out_size)
{
    const float* x   = (const float*)d_in[0];
    const float* Wq  = (const float*)d_in[1];
    const float* bq  = (const float*)d_in[2];
    const float* Wk  = (const float*)d_in[3];
    const float* bk  = (const float*)d_in[4];
    const float* Wv  = (const float*)d_in[5];
    const float* bv  = (const float*)d_in[6];
    const float* Wo  = (const float*)d_in[7];
    const float* bo  = (const float*)d_in[8];
    const float* W1  = (const float*)d_in[9];
    const float* b1  = (const float*)d_in[10];
    const float* W2  = (const float*)d_in[11];
    const float* b2  = (const float*)d_in[12];
    const float* g1  = (const float*)d_in[13];
    const float* be1 = (const float*)d_in[14];
    const float* g2  = (const float*)d_in[15];
    const float* be2 = (const float*)d_in[16];
    float* out = (float*)d_out;

    __half *xh,*qh,*kh,*vh,*ctxh,*x1h,*hh;
    __half *wqT,*wkT,*wvT,*woT,*w1T,*w2T;
    float *ao,*x1,*mlp;
    cudaGetSymbolAddress((void**)&xh,   g_xh);
    cudaGetSymbolAddress((void**)&qh,   g_qh);
    cudaGetSymbolAddress((void**)&kh,   g_kh);
    cudaGetSymbolAddress((void**)&vh,   g_vh);
    cudaGetSymbolAddress((void**)&ctxh, g_ctxh);
    cudaGetSymbolAddress((void**)&x1h,  g_x1h);
    cudaGetSymbolAddress((void**)&hh,   g_hh);
    cudaGetSymbolAddress((void**)&ao,   g_ao);
    cudaGetSymbolAddress((void**)&x1,   g_x1);
    cudaGetSymbolAddress((void**)&mlp,  g_mlp);
    cudaGetSymbolAddress((void**)&wqT,  g_wqT);
    cudaGetSymbolAddress((void**)&wkT,  g_wkT);
    cudaGetSymbolAddress((void**)&wvT,  g_wvT);
    cudaGetSymbolAddress((void**)&woT,  g_woT);
    cudaGetSymbolAddress((void**)&w1T,  g_w1T);
    cudaGetSymbolAddress((void**)&w2T,  g_w2T);

    cudaFuncSetAttribute(tgemm_k<1,0,1>, cudaFuncAttributeMaxDynamicSharedMemorySize, GEMM_SMEM_BYTES);
    cudaFuncSetAttribute(tgemm_k<0,0,0>, cudaFuncAttributeMaxDynamicSharedMemorySize, GEMM_SMEM_BYTES);
    cudaFuncSetAttribute(tgemm_k<0,1,1>, cudaFuncAttributeMaxDynamicSharedMemorySize, GEMM_SMEM_BYTES);
    cudaFuncSetAttribute(attn_k,         cudaFuncAttributeMaxDynamicSharedMemorySize, ATTN_SMEM_BYTES);

    // --- pre-pass ---
    {
        int n = TOK*DIM/4;
        roundh_k<<<(n+255)/256, 256>>>(x, xh, n);
        dim3 tg(DIM/32, DIM/32, 2);
        troundT2_k<<<tg, 256>>>(Wq, wqT, Wk, wkT, DIM, DIM);
        troundT2_k<<<tg, 256>>>(Wv, wvT, Wo, woT, DIM, DIM);
        dim3 tg12(HID/32, DIM/32, 2);
        troundT12_k<<<tg12, 256>>>(W1, w1T, W2, w2T);
    }

    const int mtiles = (TOK + 127)/128;   // 99
    const int lnBlocks = (TOK + 1)/2;     // 6304

    // --- fused QKV projection (half out, head-split; q pre-scaled) ---
    {
        dim3 grid(DIM/128, mtiles, 3);
        tgemm_k<1,0,1><<<grid, 256, GEMM_SMEM_BYTES>>>(xh, wqT, wkT, wvT, bq, bk, bv,
                                                       qh, kh, vh, TOK, DIM, DIM,
                                                       0.125f, 1.0f, 1.0f);
    }

    // --- fused attention -> ctx (half) ---
    attn_k<<<BH*4, 512, ATTN_SMEM_BYTES>>>(qh, kh, vh, ctxh);

    // --- attn_out = ctx @ Wo + bo (float out) ---
    {
        dim3 grid(DIM/128, mtiles, 1);
        tgemm_k<0,0,0><<<grid, 256, GEMM_SMEM_BYTES>>>(ctxh, woT, woT, woT, bo, bo, bo,
                                                       ao, ao, ao, TOK, DIM, DIM,
                                                       1.0f, 1.0f, 1.0f);
    }

    // --- x1 = x + LN(attn_out); half copy for MLP1 ---
    add_ln_k<<<lnBlocks, 384>>>(x, ao, g1, be1, x1, x1h, TOK);

    // --- h = gelu(x1 @ W1 + b1) (half out) ---
    {
        dim3 grid(HID/128, mtiles, 1);
        tgemm_k<0,1,1><<<grid, 256, GEMM_SMEM_BYTES>>>(x1h, w1T, w1T, w1T, b1, b1, b1,
                                                       hh, hh, hh, TOK, HID, DIM,
                                                       1.0f, 1.0f, 1.0f);
    }

    // --- mlp = h @ W2 + b2 (float out) ---
    {
        dim3 grid(DIM/128, mtiles, 1);
        tgemm_k<0,0,0><<<grid, 256, GEMM_SMEM_BYTES>>>(hh, w2T, w2T, w2T, b2, b2, b2,
                                                       mlp, mlp, mlp, TOK, DIM, HID,
                                                       1.0f, 1.0f, 1.0f);
    }

    // --- out = x1 + LN(mlp) ---
    add_ln_k<<<lnBlocks, 384>>>(x1, mlp, g2, be2, out, nullptr, TOK);
}

// round 17
// speedup vs baseline: 2.3849x; 1.0278x over previous
#include <cuda_runtime.h>
#include <cuda_fp16.h>
#include <math.h>
#include <stdint.h>

// ---------------- problem constants ----------------
#define BATCH   64
#define SEQ     197
#define TOK     (BATCH*SEQ)      // 12608
#define DIM     768
#define NHEAD   12
#define HDIM    64
#define HID     3072
#define BH      (BATCH*NHEAD)    // 768
#define LN_EPS  1e-6f

// ---------------- scratch (device globals) ----------------
__device__ __half g_xh  [(long)TOK*DIM];
__device__ __half g_qh  [(long)BH*SEQ*HDIM];
__device__ __half g_kh  [(long)BH*SEQ*HDIM];
__device__ __half g_vh  [(long)BH*SEQ*HDIM];
__device__ __half g_ctxh[(long)TOK*DIM];
__device__ __half g_x1h [(long)TOK*DIM];
__device__ __half g_hh  [(long)TOK*HID];
__device__ __half g_aoh [(long)TOK*DIM];
__device__ __half g_mlph[(long)TOK*DIM];
__device__ float  g_x1  [(long)TOK*DIM];
// transposed + fp16-rounded weights: [N][K]
__device__ __half g_wqT[DIM*DIM];
__device__ __half g_wkT[DIM*DIM];
__device__ __half g_wvT[DIM*DIM];
__device__ __half g_woT[DIM*DIM];
__device__ __half g_w1T[(long)HID*DIM];
__device__ __half g_w2T[(long)DIM*HID];

__device__ __forceinline__ float gelu_exact(float v) {
    return 0.5f * v * (1.f + erff(v * 0.70710678118654752f));
}
__device__ __forceinline__ void cpa16(uint32_t dst, const void* src) {
    asm volatile("cp.async.cg.shared.global [%0], [%1], 16;" :: "r"(dst), "l"(src) : "memory");
}
__device__ __forceinline__ void ldsm4(uint32_t addr, uint32_t& r0, uint32_t& r1,
                                      uint32_t& r2, uint32_t& r3) {
    asm volatile("ldmatrix.sync.aligned.m8n8.x4.shared.b16 {%0,%1,%2,%3}, [%4];"
                 : "=r"(r0), "=r"(r1), "=r"(r2), "=r"(r3) : "r"(addr));
}
__device__ __forceinline__ void ldsm4t(uint32_t addr, uint32_t& r0, uint32_t& r1,
                                       uint32_t& r2, uint32_t& r3) {
    asm volatile("ldmatrix.sync.aligned.m8n8.x4.trans.shared.b16 {%0,%1,%2,%3}, [%4];"
                 : "=r"(r0), "=r"(r1), "=r"(r2), "=r"(r3) : "r"(addr));
}
__device__ __forceinline__ void mma_f16(float* c, uint32_t a0, uint32_t a1,
                                        uint32_t a2, uint32_t a3,
                                        uint32_t b0, uint32_t b1) {
    asm volatile("mma.sync.aligned.m16n8k16.row.col.f32.f16.f16.f32 "
                 "{%0,%1,%2,%3}, {%4,%5,%6,%7}, {%8,%9}, {%0,%1,%2,%3};"
                 : "+f"(c[0]), "+f"(c[1]), "+f"(c[2]), "+f"(c[3])
                 : "r"(a0), "r"(a1), "r"(a2), "r"(a3), "r"(b0), "r"(b1));
}

// ---------------- float -> fp16 rounding kernel ----------------
__global__ void roundh_k(const float* __restrict__ src, __half* __restrict__ dst, int n4)
{
    int i = blockIdx.x*blockDim.x + threadIdx.x;
    if (i < n4) {
        float4 v = reinterpret_cast<const float4*>(src)[i];
        union { __half2 h[2]; uint2 u; } pk;
        pk.h[0] = __floats2half2_rn(v.x, v.y);
        pk.h[1] = __floats2half2_rn(v.z, v.w);
        reinterpret_cast<uint2*>(dst)[i] = pk.u;
    }
}

// ---------------- transpose + fp16-round: 4 DIMxDIM pairs in one launch ----------------
__global__ void troundT4_k(const float* __restrict__ s0, __half* __restrict__ d0,
                           const float* __restrict__ s1, __half* __restrict__ d1,
                           const float* __restrict__ s2, __half* __restrict__ d2,
                           const float* __restrict__ s3, __half* __restrict__ d3)
{
    const float* src; __half* dst;
    switch (blockIdx.z) {
        case 0: src = s0; dst = d0; break;
        case 1: src = s1; dst = d1; break;
        case 2: src = s2; dst = d2; break;
        default: src = s3; dst = d3; break;
    }
    __shared__ float t[32][33];
    const int n0 = blockIdx.x*32, k0 = blockIdx.y*32;
    const int tx = threadIdx.x & 31, tg = threadIdx.x >> 5;
    #pragma unroll
    for (int i=0;i<4;i++) {
        int r = tg + i*8;
        t[r][tx] = src[(size_t)(k0+r)*DIM + n0 + tx];
    }
    __syncthreads();
    #pragma unroll
    for (int i=0;i<4;i++) {
        int r = tg + i*8;
        dst[(size_t)(n0+r)*DIM + k0 + tx] = __float2half_rn(t[tx][r]);
    }
}

// W1 [DIM][HID]->[HID][DIM] (z=0) and W2 [HID][DIM]->[DIM][HID] (z=1)
__global__ void troundT12_k(const float* __restrict__ s0, __half* __restrict__ d0,
                            const float* __restrict__ s1, __half* __restrict__ d1)
{
    int K, N, n0, k0;
    const float* src;
    __half* dst;
    if (blockIdx.z == 0) {
        src = s0; dst = d0; K = DIM; N = HID;
        n0 = blockIdx.x*32; k0 = blockIdx.y*32;
    } else {
        src = s1; dst = d1; K = HID; N = DIM;
        n0 = blockIdx.y*32; k0 = blockIdx.x*32;
    }
    __shared__ float t[32][33];
    const int tx = threadIdx.x & 31, tg = threadIdx.x >> 5;
    #pragma unroll
    for (int i=0;i<4;i++) {
        int r = tg + i*8;
        t[r][tx] = src[(size_t)(k0+r)*N + n0 + tx];
    }
    __syncthreads();
    #pragma unroll
    for (int i=0;i<4;i++) {
        int r = tg + i*8;
        dst[(size_t)(n0+r)*K + k0 + tx] = __float2half_rn(t[tx][r]);
    }
}

// =====================================================================
// FP16 GEMM via ldmatrix + mma.m16n8k16 (fp32 accumulate).
// 128x128x64 tiles, 8 warps (64x32 warp tiles), 2 CTAs/SM.
// 3-stage cp.async pipeline, single __syncthreads per k-step.
// OUTHALF=1: register epilogue math -> half2 smem staging -> uint4 stores.
// OUTHALF=0: fp32 smem staging -> float4 stores.
// =====================================================================
#define APITCH 72
#define STAGE_BYTES (128*APITCH*2*2)
#define GEMM_SMEM_BYTES (3*STAGE_BYTES)

template<int OUTMODE,int EPI,int OUTHALF>
__launch_bounds__(256, 2)
__global__ void tgemm_k(const __half* __restrict__ A,
                        const __half* __restrict__ B0, const __half* __restrict__ B1, const __half* __restrict__ B2,
                        const float* __restrict__ c0, const float* __restrict__ c1, const float* __restrict__ c2,
                        void* __restrict__ D0, void* __restrict__ D1, void* __restrict__ D2,
                        int M, int N, int K, float a0, float a1, float a2)
{
    extern __shared__ char smc[];
    float*  smf = reinterpret_cast<float*>(smc);
    __half* smh = reinterpret_cast<__half*>(smc);
    const uint32_t smBase = (uint32_t)__cvta_generic_to_shared(smc);

    const int z = blockIdx.z;
    const __half* Bt  = (z==0) ? B0 : (z==1) ? B1 : B2;
    const float* bias = (z==0) ? c0 : (z==1) ? c1 : c2;
    void*        Dv   = (z==0) ? D0 : (z==1) ? D1 : D2;
    const float alpha = (z==0) ? a0 : (z==1) ? a1 : a2;

    const int tileM = blockIdx.y * 128;
    const int tileN = blockIdx.x * 128;
    const int tid   = threadIdx.x;
    const int warpId= tid >> 5;
    const int lane  = tid & 31;
    const int wm    = warpId >> 2;
    const int wn    = warpId & 3;

    const int ldRow = tid >> 3;
    const int ldCol = (tid & 7) << 3;

    const __half* aPtr[4];
    #pragma unroll
    for (int t=0;t<4;t++) {
        int gm = tileM + t*32 + ldRow;
        if (gm > M-1) gm = M-1;
        aPtr[t] = A + (size_t)gm*K + ldCol;
    }
    const __half* bPtr[4];
    #pragma unroll
    for (int t=0;t<4;t++)
        bPtr[t] = Bt + (size_t)(tileN + t*32 + ldRow)*K + ldCol;

    const int rowOff = (lane & 7) + ((lane >> 3) & 1) * 8;
    const int kOff   = (lane >> 4) * 8;

    const uint32_t aAddr0 = smBase + (uint32_t)(((wm*64 + rowOff)*APITCH + kOff) * 2);
    const uint32_t bAddr0 = smBase + (uint32_t)((128*APITCH + (wn*32 + rowOff)*APITCH + kOff) * 2);

    float acc[4][4][4];
    #pragma unroll
    for (int i=0;i<4;i++)
        #pragma unroll
        for (int j=0;j<4;j++)
            #pragma unroll
            for (int t=0;t<4;t++) acc[i][j][t] = 0.f;

    auto loadStage = [&](int k0, int st) {
        const uint32_t ab = smBase + (uint32_t)st*STAGE_BYTES;
        const uint32_t bb = ab + 128*APITCH*2;
        #pragma unroll
        for (int t=0;t<4;t++)
            cpa16(ab + (uint32_t)(((t*32 + ldRow)*APITCH + ldCol)*2), aPtr[t] + k0);
        #pragma unroll
        for (int t=0;t<4;t++)
            cpa16(bb + (uint32_t)(((t*32 + ldRow)*APITCH + ldCol)*2), bPtr[t] + k0);
        asm volatile("cp.async.commit_group;" ::: "memory");
    };

    const int NS = K >> 6;
    loadStage(0, 0);
    if (NS > 1) loadStage(64, 1);

    int st = 0;
    for (int s = 0; s < NS; s++) {
        if (s + 1 < NS) asm volatile("cp.async.wait_group 1;" ::: "memory");
        else            asm volatile("cp.async.wait_group 0;" ::: "memory");
        __syncthreads();

        if (s + 2 < NS) {
            int nst = st + 2; if (nst >= 3) nst -= 3;
            loadStage((s+2) << 6, nst);
        }

        const uint32_t aS = aAddr0 + (uint32_t)st*STAGE_BYTES;
        const uint32_t bS = bAddr0 + (uint32_t)st*STAGE_BYTES;
        #pragma unroll
        for (int ks=0; ks<4; ks++) {
            uint32_t a[4][4], b[2][4];
            #pragma unroll
            for (int mb=0; mb<4; mb++)
                ldsm4(aS + (uint32_t)(mb*16*APITCH*2 + ks*32), a[mb][0], a[mb][1], a[mb][2], a[mb][3]);
            #pragma unroll
            for (int nb=0; nb<2; nb++)
                ldsm4(bS + (uint32_t)(nb*16*APITCH*2 + ks*32), b[nb][0], b[nb][1], b[nb][2], b[nb][3]);
            #pragma unroll
            for (int mb=0; mb<4; mb++)
                #pragma unroll
                for (int j=0; j<4; j++)
                    mma_f16(acc[mb][j], a[mb][0], a[mb][1], a[mb][2], a[mb][3],
                            b[j>>1][j&1], b[j>>1][(j&1)+2]);
        }
        if (++st == 3) st = 0;
    }
    __syncthreads();

    const int r0 = lane >> 2;
    const int cb = 2*(lane & 3);

    if (OUTHALF == 0) {
        #pragma unroll
        for (int mb=0; mb<4; mb++) {
            #pragma unroll
            for (int j=0; j<4; j++) {
                int row = wm*64 + mb*16 + r0;
                int col = wn*32 + j*8 + cb;
                *reinterpret_cast<float2*>(&smf[row*132 + col])     = make_float2(acc[mb][j][0], acc[mb][j][1]);
                *reinterpret_cast<float2*>(&smf[(row+8)*132 + col]) = make_float2(acc[mb][j][2], acc[mb][j][3]);
            }
        }
        __syncthreads();
        const int row = tid >> 1;
        const int gm  = tileM + row;
        if (gm < M) {
            float* C = reinterpret_cast<float*>(Dv);
            #pragma unroll
            for (int f=0; f<16; f++) {
                int c  = (tid & 1)*64 + f*4;
                int gn = tileN + c;
                float4 v = *reinterpret_cast<const float4*>(&smf[row*132 + c]);
                v.x = (v.x + bias[gn  ]) * alpha;
                v.y = (v.y + bias[gn+1]) * alpha;
                v.z = (v.z + bias[gn+2]) * alpha;
                v.w = (v.w + bias[gn+3]) * alpha;
                if (EPI == 1) {
                    v.x = gelu_exact(v.x); v.y = gelu_exact(v.y);
                    v.z = gelu_exact(v.z); v.w = gelu_exact(v.w);
                }
                *reinterpret_cast<float4*>(&C[(size_t)gm*N + gn]) = v;
            }
        }
    } else {
        float bx[4], by[4];
        #pragma unroll
        for (int j=0;j<4;j++) {
            int gn = tileN + wn*32 + j*8 + cb;
            bx[j] = bias[gn];
            by[j] = bias[gn+1];
        }
        #pragma unroll
        for (int mb=0; mb<4; mb++) {
            #pragma unroll
            for (int j=0; j<4; j++) {
                int row = wm*64 + mb*16 + r0;
                int col = wn*32 + j*8 + cb;
                float v0 = (acc[mb][j][0] + bx[j]) * alpha;
                float v1 = (acc[mb][j][1] + by[j]) * alpha;
                float v2 = (acc[mb][j][2] + bx[j]) * alpha;
                float v3 = (acc[mb][j][3] + by[j]) * alpha;
                if (EPI == 1) {
                    v0 = gelu_exact(v0); v1 = gelu_exact(v1);
                    v2 = gelu_exact(v2); v3 = gelu_exact(v3);
                }
                *reinterpret_cast<__half2*>(&smh[row*136 + col])     = __floats2half2_rn(v0, v1);
                *reinterpret_cast<__half2*>(&smh[(row+8)*136 + col]) = __floats2half2_rn(v2, v3);
            }
        }
        __syncthreads();
        const int row = tid >> 1;
        const int gm  = tileM + row;
        if (gm < M) {
            __half* C = reinterpret_cast<__half*>(Dv);
            int b = 0, s = 0;
            if (OUTMODE == 1) { b = gm / SEQ; s = gm - b*SEQ; }
            #pragma unroll
            for (int f=0; f<8; f++) {
                int c  = (tid & 1)*64 + f*8;
                int gn = tileN + c;
                uint4 u = *reinterpret_cast<const uint4*>(&smh[row*136 + c]);
                if (OUTMODE == 0) {
                    *reinterpret_cast<uint4*>(&C[(size_t)gm*N + gn]) = u;
                } else {
                    int h = gn >> 6, dd = gn & 63;
                    size_t orow = (size_t)(b*NHEAD + h)*SEQ + s;
                    *reinterpret_cast<uint4*>(&C[orow*HDIM + dd]) = u;
                }
            }
        }
    }
}

// =====================================================================
// Fused attention, fp16 (R14/R15 configuration, proven).
// =====================================================================
#define AT_KP 72
#define AT_TP 216
#define AT_SP 212
#define OFFB_K 0
#define OFFB_V (208*AT_KP*2)
#define OFFB_Q (OFFB_V + 208*AT_KP*2)
#define OFFB_S (OFFB_Q + 64*AT_KP*2)
#define OFFB_P (OFFB_S + 64*AT_SP*4)
#define ATTN_SMEM_BYTES (OFFB_P + 64*AT_TP*2)

__launch_bounds__(512)
__global__ void attn_k(const __half* __restrict__ q, const __half* __restrict__ k,
                       const __half* __restrict__ v, __half* __restrict__ ctx)
{
    extern __shared__ char smc[];
    const uint32_t smBase = (uint32_t)__cvta_generic_to_shared(smc);
    __half* Kh = reinterpret_cast<__half*>(smc + OFFB_K);
    __half* Vh = reinterpret_cast<__half*>(smc + OFFB_V);
    __half* Qh = reinterpret_cast<__half*>(smc + OFFB_Q);
    float*  Sf = reinterpret_cast<float*>(smc + OFFB_S);
    __half* Ph = reinterpret_cast<__half*>(smc + OFFB_P);

    const int bh   = blockIdx.x >> 2;
    const int tile = blockIdx.x & 3;
    const int s0   = tile * 64;
    const int valid = (SEQ - s0) < 64 ? (SEQ - s0) : 64;
    const int miMax = (valid + 15) >> 4;

    const int b  = bh / NHEAD;
    const int h  = bh - b*NHEAD;
    const int tid    = threadIdx.x;
    const int warpId = tid >> 5;
    const int lane   = tid & 31;

    const __half* qb = q + (size_t)bh*SEQ*HDIM;
    const __half* kb = k + (size_t)bh*SEQ*HDIM;
    const __half* vb = v + (size_t)bh*SEQ*HDIM;

    const int rowOff = (lane & 7) + ((lane >> 3) & 1) * 8;
    const int kOff   = (lane >> 4) * 8;
    const int r0 = lane >> 2;
    const int cb = 2*(lane & 3);

    const uint4 zero4 = make_uint4(0u,0u,0u,0u);

    for (int idx = tid; idx < 208*8; idx += 512) {
        int t = idx >> 3, f = idx & 7;
        uint4 kv = (t < SEQ) ? *reinterpret_cast<const uint4*>(kb + (size_t)t*HDIM + f*8) : zero4;
        uint4 vv = (t < SEQ) ? *reinterpret_cast<const uint4*>(vb + (size_t)t*HDIM + f*8) : zero4;
        *reinterpret_cast<uint4*>(Kh + t*AT_KP + f*8) = kv;
        *reinterpret_cast<uint4*>(Vh + t*AT_KP + f*8) = vv;
    }
    for (int idx = tid; idx < 64*8; idx += 512) {
        int r = idx >> 3, f = idx & 7;
        int s = s0 + r;
        uint4 val = (s < SEQ) ? *reinterpret_cast<const uint4*>(qb + (size_t)s*HDIM + f*8) : zero4;
        *reinterpret_cast<uint4*>(Qh + r*AT_KP + f*8) = val;
    }
    __syncthreads();

    for (int t = warpId; t < miMax*13; t += 16) {
        int mi = t / 13, ni = t - (t/13)*13;
        float c0[4] = {0.f,0.f,0.f,0.f}, c1[4] = {0.f,0.f,0.f,0.f};
        const uint32_t aAddr = smBase + OFFB_Q + (uint32_t)(((mi*16 + rowOff)*AT_KP + kOff)*2);
        const uint32_t bAddr = smBase + OFFB_K + (uint32_t)(((ni*16 + rowOff)*AT_KP + kOff)*2);
        #pragma unroll
        for (int ks=0; ks<4; ks++) {
            uint32_t a0,a1,a2,a3, b0,b1,b2,b3;
            ldsm4(aAddr + ks*32, a0,a1,a2,a3);
            ldsm4(bAddr + ks*32, b0,b1,b2,b3);
            mma_f16(c0, a0,a1,a2,a3, b0,b2);
            mma_f16(c1, a0,a1,a2,a3, b1,b3);
        }
        {
            int row = mi*16 + r0, col = ni*16 + cb;
            *reinterpret_cast<float2*>(&Sf[row*AT_SP + col])         = make_float2(c0[0], c0[1]);
            *reinterpret_cast<float2*>(&Sf[(row+8)*AT_SP + col])     = make_float2(c0[2], c0[3]);
            *reinterpret_cast<float2*>(&Sf[row*AT_SP + col + 8])     = make_float2(c1[0], c1[1]);
            *reinterpret_cast<float2*>(&Sf[(row+8)*AT_SP + col + 8]) = make_float2(c1[2], c1[3]);
        }
    }
    __syncthreads();

    for (int rr = 0; rr < miMax; rr++) {
        int r = rr*16 + warpId;
        float* rowp = &Sf[r*AT_SP];
        float x[7];
        float m = -1e30f;
        #pragma unroll
        for (int i=0;i<7;i++) {
            int c = lane + i*32;
            x[i] = (c < SEQ) ? rowp[c] : -1e30f;
            m = fmaxf(m, x[i]);
        }
        #pragma unroll
        for (int o=16;o;o>>=1) m = fmaxf(m, __shfl_xor_sync(0xffffffffu, m, o));
        float sum = 0.f;
        #pragma unroll
        for (int i=0;i<7;i++) { x[i] = __expf(x[i] - m); sum += x[i]; }
        #pragma unroll
        for (int o=16;o;o>>=1) sum += __shfl_xor_sync(0xffffffffu, sum, o);
        float inv = 1.f / sum;
        #pragma unroll
        for (int i=0;i<7;i++) {
            int c = lane + i*32;
            if (c < SEQ)      Ph[r*AT_TP + c] = __float2half_rn(x[i]*inv);
            else if (c < 208) Ph[r*AT_TP + c] = __float2half(0.f);
        }
    }
    __syncthreads();

    if (warpId < miMax*4) {
        int mi = warpId >> 2, ni = warpId & 3;
        float c0[4] = {0.f,0.f,0.f,0.f}, c1[4] = {0.f,0.f,0.f,0.f};
        const uint32_t aAddr = smBase + OFFB_P + (uint32_t)(((mi*16 + rowOff)*AT_TP + kOff)*2);
        const uint32_t bAddr = smBase + OFFB_V + (uint32_t)((rowOff*AT_KP + ni*16 + kOff)*2);
        #pragma unroll
        for (int ks=0; ks<13; ks++) {
            uint32_t a0,a1,a2,a3, b0,b1,b2,b3;
            ldsm4 (aAddr + ks*32,                     a0,a1,a2,a3);
            ldsm4t(bAddr + (uint32_t)(ks*16*AT_KP*2), b0,b1,b2,b3);
            mma_f16(c0, a0,a1,a2,a3, b0,b1);
            mma_f16(c1, a0,a1,a2,a3, b2,b3);
        }
        {
            int row = mi*16 + r0, col = ni*16 + cb;
            *reinterpret_cast<__half2*>(Qh + row*AT_KP + col)       = __floats2half2_rn(c0[0], c0[1]);
            *reinterpret_cast<__half2*>(Qh + (row+8)*AT_KP + col)   = __floats2half2_rn(c0[2], c0[3]);
            *reinterpret_cast<__half2*>(Qh + row*AT_KP + col+8)     = __floats2half2_rn(c1[0], c1[1]);
            *reinterpret_cast<__half2*>(Qh + (row+8)*AT_KP + col+8) = __floats2half2_rn(c1[2], c1[3]);
        }
    }
    __syncthreads();

    for (int idx = tid; idx < valid*8; idx += 512) {
        int r = idx >> 3, f = idx & 7;
        int s = s0 + r;
        uint4 val = *reinterpret_cast<const uint4*>(Qh + r*AT_KP + f*8);
        *reinterpret_cast<uint4*>(ctx + ((size_t)(b*SEQ + s))*DIM + h*HDIM + f*8) = val;
    }
}

// ---------------- residual + LayerNorm: 2 rows per CTA, half y input ----------------
__launch_bounds__(384)
__global__ void add_ln_k(const float* __restrict__ x, const __half* __restrict__ y,
                         const float* __restrict__ g, const float* __restrict__ be,
                         float* __restrict__ out, __half* __restrict__ outR, int rows)
{
    const int sub = threadIdx.x / 192;
    const int t   = threadIdx.x - sub*192;
    const int r   = blockIdx.x*2 + sub;
    if (r >= rows) return;

    const uint2 yu = *reinterpret_cast<const uint2*>(y + (size_t)r*DIM + t*4);
    union { uint2 u; __half2 h[2]; } yp; yp.u = yu;
    float2 y01 = __half22float2(yp.h[0]);
    float2 y23 = __half22float2(yp.h[1]);
    float4 yv = make_float4(y01.x, y01.y, y23.x, y23.y);

    float s  = yv.x + yv.y + yv.z + yv.w;
    float sq = yv.x*yv.x + yv.y*yv.y + yv.z*yv.z + yv.w*yv.w;

    __shared__ float red[2][16];
    #pragma unroll
    for (int o=16;o;o>>=1) { s += __shfl_xor_sync(0xffffffffu, s, o); sq += __shfl_xor_sync(0xffffffffu, sq, o); }
    int w = t >> 5, lane = t & 31;
    if (lane == 0) { red[sub][w] = s; red[sub][w+8] = sq; }
    __syncthreads();
    if (t < 32) {
        s  = (lane < 6) ? red[sub][lane]     : 0.f;
        sq = (lane < 6) ? red[sub][lane + 8] : 0.f;
        #pragma unroll
        for (int o=4;o;o>>=1) { s += __shfl_xor_sync(0xffffffffu, s, o); sq += __shfl_xor_sync(0xffffffffu, sq, o); }
        if (lane == 0) { red[sub][0] = s; red[sub][1] = sq; }
    }
    __syncthreads();
    const float mu   = red[sub][0] * (1.f/DIM);
    const float var  = red[sub][1] * (1.f/DIM) - mu*mu;
    const float rstd = rsqrtf(var + LN_EPS);

    const float4 xv = *reinterpret_cast<const float4*>(&x[(size_t)r*DIM + t*4]);
    const float4 gv = *reinterpret_cast<const float4*>(&g[t*4]);
    const float4 bv = *reinterpret_cast<const float4*>(&be[t*4]);
    float4 o;
    o.x = xv.x + (yv.x - mu)*rstd*gv.x + bv.x;
    o.y = xv.y + (yv.y - mu)*rstd*gv.y + bv.y;
    o.z = xv.z + (yv.z - mu)*rstd*gv.z + bv.z;
    o.w = xv.w + (yv.w - mu)*rstd*gv.w + bv.w;
    *reinterpret_cast<float4*>(&out[(size_t)r*DIM + t*4]) = o;
    if (outR) {
        union { __half2 h[2]; uint2 u; } pk;
        pk.h[0] = __floats2half2_rn(o.x, o.y);
        pk.h[1] = __floats2half2_rn(o.z, o.w);
        *reinterpret_cast<uint2*>(outR + (size_t)r*DIM + t*4) = pk.u;
    }
}

// ---------------- launch ----------------
extern "C" void kernel_launch(void* const* d_in, const int* in_sizes, int n_in,
                              void* d_out, int out_size)
{
    const float* x   = (const float*)d_in[0];
    const float* Wq  = (const float*)d_in[1];
    const float* bq  = (const float*)d_in[2];
    const float* Wk  = (const float*)d_in[3];
    const float* bk  = (const float*)d_in[4];
    const float* Wv  = (const float*)d_in[5];
    const float* bv  = (const float*)d_in[6];
    const float* Wo  = (const float*)d_in[7];
    const float* bo  = (const float*)d_in[8];
    const float* W1  = (const float*)d_in[9];
    const float* b1  = (const float*)d_in[10];
    const float* W2  = (const float*)d_in[11];
    const float* b2  = (const float*)d_in[12];
    const float* g1  = (const float*)d_in[13];
    const float* be1 = (const float*)d_in[14];
    const float* g2  = (const float*)d_in[15];
    const float* be2 = (const float*)d_in[16];
    float* out = (float*)d_out;

    __half *xh,*qh,*kh,*vh,*ctxh,*x1h,*hh,*aoh,*mlph;
    __half *wqT,*wkT,*wvT,*woT,*w1T,*w2T;
    float *x1;
    cudaGetSymbolAddress((void**)&xh,   g_xh);
    cudaGetSymbolAddress((void**)&qh,   g_qh);
    cudaGetSymbolAddress((void**)&kh,   g_kh);
    cudaGetSymbolAddress((void**)&vh,   g_vh);
    cudaGetSymbolAddress((void**)&ctxh, g_ctxh);
    cudaGetSymbolAddress((void**)&x1h,  g_x1h);
    cudaGetSymbolAddress((void**)&hh,   g_hh);
    cudaGetSymbolAddress((void**)&aoh,  g_aoh);
    cudaGetSymbolAddress((void**)&mlph, g_mlph);
    cudaGetSymbolAddress((void**)&x1,   g_x1);
    cudaGetSymbolAddress((void**)&wqT,  g_wqT);
    cudaGetSymbolAddress((void**)&wkT,  g_wkT);
    cudaGetSymbolAddress((void**)&wvT,  g_wvT);
    cudaGetSymbolAddress((void**)&woT,  g_woT);
    cudaGetSymbolAddress((void**)&w1T,  g_w1T);
    cudaGetSymbolAddress((void**)&w2T,  g_w2T);

    cudaFuncSetAttribute(tgemm_k<1,0,1>, cudaFuncAttributeMaxDynamicSharedMemorySize, GEMM_SMEM_BYTES);
    cudaFuncSetAttribute(tgemm_k<0,0,1>, cudaFuncAttributeMaxDynamicSharedMemorySize, GEMM_SMEM_BYTES);
    cudaFuncSetAttribute(tgemm_k<0,1,1>, cudaFuncAttributeMaxDynamicSharedMemorySize, GEMM_SMEM_BYTES);
    cudaFuncSetAttribute(attn_k,         cudaFuncAttributeMaxDynamicSharedMemorySize, ATTN_SMEM_BYTES);

    // --- pre-pass ---
    {
        int n = TOK*DIM/4;
        roundh_k<<<(n+255)/256, 256>>>(x, xh, n);
        dim3 tg(DIM/32, DIM/32, 4);
        troundT4_k<<<tg, 256>>>(Wq, wqT, Wk, wkT, Wv, wvT, Wo, woT);
        dim3 tg12(HID/32, DIM/32, 2);
        troundT12_k<<<tg12, 256>>>(W1, w1T, W2, w2T);
    }

    const int mtiles = (TOK + 127)/128;   // 99
    const int lnBlocks = (TOK + 1)/2;     // 6304

    // --- fused QKV projection (half out, head-split; q pre-scaled) ---
    {
        dim3 grid(DIM/128, mtiles, 3);
        tgemm_k<1,0,1><<<grid, 256, GEMM_SMEM_BYTES>>>(xh, wqT, wkT, wvT, bq, bk, bv,
                                                       qh, kh, vh, TOK, DIM, DIM,
                                                       0.125f, 1.0f, 1.0f);
    }

    // --- fused attention -> ctx (half) ---
    attn_k<<<BH*4, 512, ATTN_SMEM_BYTES>>>(qh, kh, vh, ctxh);

    // --- attn_out = ctx @ Wo + bo (half out) ---
    {
        dim3 grid(DIM/128, mtiles, 1);
        tgemm_k<0,0,1><<<grid, 256, GEMM_SMEM_BYTES>>>(ctxh, woT, woT, woT, bo, bo, bo,
                                                       aoh, aoh, aoh, TOK, DIM, DIM,
                                                       1.0f, 1.0f, 1.0f);
    }

    // --- x1 = x + LN(attn_out); half copy for MLP1 ---
    add_ln_k<<<lnBlocks, 384>>>(x, aoh, g1, be1, x1, x1h, TOK);

    // --- h = gelu(x1 @ W1 + b1) (half out) ---
    {
        dim3 grid(HID/128, mtiles, 1);
        tgemm_k<0,1,1><<<grid, 256, GEMM_SMEM_BYTES>>>(x1h, w1T, w1T, w1T, b1, b1, b1,
                                                       hh, hh, hh, TOK, HID, DIM,
                                                       1.0f, 1.0f, 1.0f);
    }

    // --- mlp = h @ W2 + b2 (half out) ---
    {
        dim3 grid(DIM/128, mtiles, 1);
        tgemm_k<0,0,1><<<grid, 256, GEMM_SMEM_BYTES>>>(hh, w2T, w2T, w2T, b2, b2, b2,
                                                       mlph, mlph, mlph, TOK, DIM, HID,
                                                       1.0f, 1.0f, 1.0f);
    }

    // --- out = x1 + LN(mlp) ---
    add_ln_k<<<lnBlocks, 384>>>(x1, mlph, g2, be2, out, nullptr, TOK);
}